// round 8
// baseline (speedup 1.0000x reference)
#include <cuda_runtime.h>
#include <cuda_fp16.h>
#include <math.h>
#include <stdint.h>

#define B_   4
#define T_   2048
#define C_   1024
#define H_   16
#define D_   64
#define M_   (B_ * T_)           // 8192 rows
#define LN_EPS 1e-5f

// ---------------- scratch (static device globals; no allocation) -----------
__device__ __align__(128) float g_att[(size_t)M_ * C_];
__device__ __align__(128) float g_x1 [(size_t)M_ * C_];
__device__ __align__(128) float g_mlp[(size_t)M_ * C_];
__device__ __align__(128) __half g_qkvh[(size_t)M_ * 3 * C_];
__device__ __align__(128) __half g_qkvl[(size_t)M_ * 3 * C_];
__device__ __align__(128) __half g_ah [(size_t)M_ * C_];       // A hi (x / x1)
__device__ __align__(128) __half g_al [(size_t)M_ * C_];
__device__ __align__(128) __half g_ah2[(size_t)M_ * 4 * C_];   // gelu(h) hi
__device__ __align__(128) __half g_al2[(size_t)M_ * 4 * C_];
__device__ __align__(128) __half g_bh [(size_t)4 * C_ * C_];   // B hi [N,K] (single-rounded)

__device__ __forceinline__ float gelu_exact(float x) {
    return 0.5f * x * (1.0f + erff(x * 0.70710678118654752440f));
}

// ---------------- PTX helpers ----------------------------------------------
__device__ __forceinline__ uint32_t smem_u32(const void* p) {
    uint32_t a;
    asm("{ .reg .u64 t; cvta.to.shared.u64 t, %1; cvt.u32.u64 %0, t; }" : "=r"(a) : "l"(p));
    return a;
}
#define CP16(s, g) asm volatile("cp.async.cg.shared.global [%0], [%1], 16;" :: "r"(s), "l"(g))
#define CP_COMMIT() asm volatile("cp.async.commit_group;" ::: "memory")
#define CP_WAIT1()  asm volatile("cp.async.wait_group 1;" ::: "memory")
#define CP_WAIT0()  asm volatile("cp.async.wait_group 0;" ::: "memory")

__device__ __forceinline__ void ldsm4(uint32_t& r0, uint32_t& r1,
                                      uint32_t& r2, uint32_t& r3, uint32_t addr) {
    asm volatile("ldmatrix.sync.aligned.m8n8.x4.shared.b16 {%0,%1,%2,%3}, [%4];"
                 : "=r"(r0), "=r"(r1), "=r"(r2), "=r"(r3) : "r"(addr));
}
__device__ __forceinline__ void ldsm4t(uint32_t& r0, uint32_t& r1,
                                       uint32_t& r2, uint32_t& r3, uint32_t addr) {
    asm volatile("ldmatrix.sync.aligned.m8n8.x4.trans.shared.b16 {%0,%1,%2,%3}, [%4];"
                 : "=r"(r0), "=r"(r1), "=r"(r2), "=r"(r3) : "r"(addr));
}
// NOT volatile: register-only op, let ptxas schedule around RAW chains.
#define MMA16816(c, a, b)                                                     \
    asm("mma.sync.aligned.m16n8k16.row.col.f32.f16.f16.f32 "                  \
        "{%0,%1,%2,%3}, {%4,%5,%6,%7}, {%8,%9}, {%0,%1,%2,%3};"               \
        : "+f"((c)[0]), "+f"((c)[1]), "+f"((c)[2]), "+f"((c)[3])              \
        : "r"((a)[0]), "r"((a)[1]), "r"((a)[2]), "r"((a)[3]),                 \
          "r"((b)[0]), "r"((b)[1]))

__device__ __forceinline__ uint32_t pack_f16x2(float lo, float hi) {
    uint32_t r;
    asm("cvt.rn.f16x2.f32 %0, %1, %2;" : "=r"(r) : "f"(hi), "f"(lo));
    return r;
}
// split (x,y) into hi f16x2 + residual-lo f16x2
__device__ __forceinline__ void split_pack2(float x, float y, uint32_t& hi, uint32_t& lo) {
    float hx = __half2float(__float2half_rn(x));
    float hy = __half2float(__float2half_rn(y));
    hi = pack_f16x2(hx, hy);
    lo = pack_f16x2(x - hx, y - hy);
}

// ---------------- split kernels --------------------------------------------
__global__ void __launch_bounds__(256) split_act(
    const float* __restrict__ X, __half* __restrict__ Hh,
    __half* __restrict__ Ll, size_t n4)
{
    size_t i = (size_t)blockIdx.x * blockDim.x + threadIdx.x;
    if (i >= n4) return;
    float4 v = ((const float4*)X)[i];
    uint32_t h0, l0, h1, l1;
    split_pack2(v.x, v.y, h0, l0);
    split_pack2(v.z, v.w, h1, l1);
    ((uint32_t*)Hh)[2 * i] = h0; ((uint32_t*)Hh)[2 * i + 1] = h1;
    ((uint32_t*)Ll)[2 * i] = l0; ((uint32_t*)Ll)[2 * i + 1] = l1;
}

// W [K,N] fp32 -> Bh [N,K] fp16 (transpose + single rounding)
__global__ void __launch_bounds__(256) round_w_t(
    const float* __restrict__ W, __half* __restrict__ Bh, int K, int N)
{
    __shared__ float t[32][33];
    const int tx = threadIdx.x, ty = threadIdx.y;   // block (32,8)
    const int n0 = blockIdx.x * 32, k0 = blockIdx.y * 32;
#pragma unroll
    for (int r = 0; r < 4; r++)
        t[ty + r * 8][tx] = W[(size_t)(k0 + ty + r * 8) * N + n0 + tx];
    __syncthreads();
#pragma unroll
    for (int r = 0; r < 4; r++) {
        int nn = ty + r * 8;
        Bh[(size_t)(n0 + nn) * K + k0 + tx] = __float2half_rn(t[tx][nn]);
    }
}

// ---------------- HMMA split-fp16 GEMM --------------------------------------
// C = Ah@Bh^T + Al@Bh^T + bias  (A 2-term fp16, B single-rounded fp16)
// CTA tile 256x128, warp tile 64x64 (8 warps = 4m x 2n), BK=32, 3 stages.
// MODE 0: fp32 out; MODE 1: split fp16 out, cols<C_ scaled 0.125 (QKV);
// MODE 2: gelu then split fp16 out.
#define GM_BK    32
#define GM_ROWB  80
#define GM_AOP   (256 * GM_ROWB)              // 20480
#define GM_BOP   (128 * GM_ROWB)              // 10240
#define GM_STAGE (2 * GM_AOP + GM_BOP)        // 51200
#define GM_SMEM  (3 * GM_STAGE)               // 153600

template <int MODE>
__global__ void __launch_bounds__(256, 1) gemm_mma(
    const __half* __restrict__ Ah, const __half* __restrict__ Al,
    const __half* __restrict__ Bh,
    const float* __restrict__ bias, float* __restrict__ Cmat,
    __half* __restrict__ Oh, __half* __restrict__ Ol,
    int N, int K)
{
    extern __shared__ char smem[];
    const uint32_t sb = smem_u32(smem);
    const int tid  = threadIdx.x;
    const int lane = tid & 31;
    const int wid  = tid >> 5;
    const int m0 = blockIdx.y * 256;
    const int n0 = blockIdx.x * 128;
    const int wm = (wid >> 1) * 64;
    const int wn = (wid & 1) * 64;

    const int nch = K / GM_BK;

    auto load_chunk = [&](int c) {
        const int kk = c * GM_BK;
        const uint32_t st = sb + (c % 3) * GM_STAGE;
#pragma unroll
        for (int i = 0; i < 4; i++) {                // A hi+lo: 1024 units each
            int u = tid + i * 256;
            int r = u >> 2, cc = u & 3;
            uint32_t so = r * GM_ROWB + cc * 16;
            size_t ga = (size_t)(m0 + r) * K + kk + cc * 8;
            CP16(st + so,          Ah + ga);
            CP16(st + GM_AOP + so, Al + ga);
        }
#pragma unroll
        for (int i = 0; i < 2; i++) {                // B hi: 512 units
            int u = tid + i * 256;
            int r = u >> 2, cc = u & 3;
            uint32_t so = r * GM_ROWB + cc * 16;
            CP16(st + 2 * GM_AOP + so, Bh + (size_t)(n0 + r) * K + kk + cc * 8);
        }
    };

    float acc[4][8][4];
#pragma unroll
    for (int i = 0; i < 4; i++)
#pragma unroll
        for (int j = 0; j < 8; j++)
#pragma unroll
            for (int t = 0; t < 4; t++) acc[i][j][t] = 0.f;

    load_chunk(0); CP_COMMIT();
    load_chunk(1); CP_COMMIT();

    const int a_row = lane & 15;
    const int a_off = (lane >> 4) * 16;
    const int b_row = (lane & 7) + ((lane >> 4) << 3);
    const int b_off = ((lane >> 3) & 1) * 16;

    for (int k = 0; k < nch; k++) {
        CP_WAIT1();
        __syncthreads();
        if (k + 2 < nch) { load_chunk(k + 2); CP_COMMIT(); }

        const uint32_t stA = sb + (k % 3) * GM_STAGE;
        const uint32_t stB = stA + 2 * GM_AOP;

#pragma unroll
        for (int ks = 0; ks < 2; ks++) {
            uint32_t ah[4][4], al[4][4];
#pragma unroll
            for (int mb = 0; mb < 4; mb++) {
                uint32_t ad = stA + (wm + mb * 16 + a_row) * GM_ROWB + ks * 32 + a_off;
                ldsm4(ah[mb][0], ah[mb][1], ah[mb][2], ah[mb][3], ad);
                ldsm4(al[mb][0], al[mb][1], al[mb][2], al[mb][3], ad + GM_AOP);
            }
#pragma unroll
            for (int nbp = 0; nbp < 4; nbp++) {
                uint32_t bd = stB + (wn + nbp * 16 + b_row) * GM_ROWB + ks * 32 + b_off;
                uint32_t h0, h1, h2, h3;
                ldsm4(h0, h1, h2, h3, bd);
                uint32_t b0h[2] = {h0, h1}, b1h[2] = {h2, h3};
                // same-accumulator MMAs are 8 apart (hi pass then lo pass)
#pragma unroll
                for (int mb = 0; mb < 4; mb++) MMA16816(acc[mb][2 * nbp],     ah[mb], b0h);
#pragma unroll
                for (int mb = 0; mb < 4; mb++) MMA16816(acc[mb][2 * nbp + 1], ah[mb], b1h);
#pragma unroll
                for (int mb = 0; mb < 4; mb++) MMA16816(acc[mb][2 * nbp],     al[mb], b0h);
#pragma unroll
                for (int mb = 0; mb < 4; mb++) MMA16816(acc[mb][2 * nbp + 1], al[mb], b1h);
            }
        }
    }

    // ---- epilogue ----
    const int gr = lane >> 2;
    const int gc = (lane & 3) * 2;
#pragma unroll
    for (int mb = 0; mb < 4; mb++) {
#pragma unroll
        for (int nb = 0; nb < 8; nb++) {
            int row = m0 + wm + mb * 16 + gr;
            int col = n0 + wn + nb * 8 + gc;
            float b0 = __ldg(&bias[col]), b1 = __ldg(&bias[col + 1]);
            float v0 = acc[mb][nb][0] + b0, v1 = acc[mb][nb][1] + b1;
            float v2 = acc[mb][nb][2] + b0, v3 = acc[mb][nb][3] + b1;
            if (MODE == 0) {
                *(float2*)(Cmat + (size_t)row * N + col)       = make_float2(v0, v1);
                *(float2*)(Cmat + (size_t)(row + 8) * N + col) = make_float2(v2, v3);
            } else {
                if (MODE == 1 && col < C_) { v0 *= 0.125f; v1 *= 0.125f; v2 *= 0.125f; v3 *= 0.125f; }
                if (MODE == 2) {
                    v0 = gelu_exact(v0); v1 = gelu_exact(v1);
                    v2 = gelu_exact(v2); v3 = gelu_exact(v3);
                }
                uint32_t h01, l01, h23, l23;
                split_pack2(v0, v1, h01, l01);
                split_pack2(v2, v3, h23, l23);
                *(uint32_t*)(Oh + (size_t)row * N + col)       = h01;
                *(uint32_t*)(Ol + (size_t)row * N + col)       = l01;
                *(uint32_t*)(Oh + (size_t)(row + 8) * N + col) = h23;
                *(uint32_t*)(Ol + (size_t)(row + 8) * N + col) = l23;
            }
        }
    }
}

// ---------------- tensor-core causal flash attention ------------------------
// 128 queries per CTA (8 warps x 16 rows), 64-key tiles, 3-term fp16 MMAs.
#define AT_ROWB  144
#define AQ_T     (128 * AT_ROWB)             // 18432 per Q operand
#define AK_T     (64 * AT_ROWB)              // 9216 per K/V operand
#define AT_STAGE (4 * AK_T)                  // Kh,Kl,Vh,Vl = 36864
#define AT_SMEM  (2 * AQ_T + 2 * AT_STAGE)   // 110592

__global__ void __launch_bounds__(256, 1) attn_tc(
    const __half* __restrict__ qkvh,
    const __half* __restrict__ qkvl,
    float* __restrict__ y)
{
    extern __shared__ char smem[];
    const uint32_t sb = smem_u32(smem);
    const int tid = threadIdx.x, lane = tid & 31, wid = tid >> 5;
    const int qb = (int)gridDim.x - 1 - (int)blockIdx.x;   // big blocks first
    const int h = blockIdx.y, b = blockIdx.z;
    const int q0 = qb * 128;
    const int wq = wid * 16;
    const int gr = lane >> 2, gc = lane & 3;
    const int RS = 3 * C_;

    const __half* qh = qkvh + (size_t)b * T_ * RS + h * D_;
    const __half* ql = qkvl + (size_t)b * T_ * RS + h * D_;
    const __half* kh = qh + C_;
    const __half* kl = ql + C_;
    const __half* vh = qh + 2 * C_;
    const __half* vl = ql + 2 * C_;

    const uint32_t QH  = sb;
    const uint32_t ST0 = sb + 2 * AQ_T;

    // load Q (hi/lo) tile: 128 rows x 128B each
#pragma unroll
    for (int t = 0; t < 2; t++) {
        const __half* g = t ? ql : qh;
#pragma unroll
        for (int i = 0; i < 4; i++) {
            int u = tid + i * 256;          // 0..1023
            int r = u >> 3, c = u & 7;
            CP16(QH + t * AQ_T + r * AT_ROWB + c * 16, g + (size_t)(q0 + r) * RS + c * 8);
        }
    }

    auto load_tile = [&](int kt, int bufsel) {
        uint32_t st = ST0 + bufsel * AT_STAGE;
#pragma unroll
        for (int t = 0; t < 4; t++) {
            const __half* g = (t == 0 ? kh : t == 1 ? kl : t == 2 ? vh : vl);
#pragma unroll
            for (int i = 0; i < 2; i++) {
                int u = tid + i * 256;      // 0..511
                int r = u >> 3, c = u & 7;
                CP16(st + t * AK_T + r * AT_ROWB + c * 16, g + (size_t)(kt * 64 + r) * RS + c * 8);
            }
        }
    };
    load_tile(0, 0);
    CP_COMMIT();
    CP_WAIT0();
    __syncthreads();

    // Q fragments
    uint32_t qfh[4][4], qfl[4][4];
    const int a_row = lane & 15, a_off = (lane >> 4) * 16;
#pragma unroll
    for (int ks = 0; ks < 4; ks++) {
        uint32_t ad = QH + (wq + a_row) * AT_ROWB + ks * 32 + a_off;
        ldsm4(qfh[ks][0], qfh[ks][1], qfh[ks][2], qfh[ks][3], ad);
        ldsm4(qfl[ks][0], qfl[ks][1], qfl[ks][2], qfl[ks][3], ad + AQ_T);
    }

    float Oacc[8][4];
#pragma unroll
    for (int i = 0; i < 8; i++)
#pragma unroll
        for (int j = 0; j < 4; j++) Oacc[i][j] = 0.f;
    float m0 = -1e30f, m1 = -1e30f, l0 = 0.f, l1 = 0.f;

    const int nt = 2 * qb + 2;
    const int b_row = (lane & 7) + ((lane >> 4) << 3);
    const int b_off = ((lane >> 3) & 1) * 16;
    const int v_row = (lane & 7) + ((lane >> 3) & 1) * 8;
    const int v_off = (lane >> 4) * 16;

    for (int kt = 0; kt < nt; kt++) {
        if (kt + 1 < nt) { load_tile(kt + 1, (kt + 1) & 1); CP_COMMIT(); }
        const uint32_t st = ST0 + (kt & 1) * AT_STAGE;

        // warp-level skip: keys all strictly above this warp's queries
        const bool active = (kt * 64) <= (q0 + wq + 15);
        if (active) {
            // ---- S = Q @ K^T (3-term split) ----
            float sacc[8][4];
#pragma unroll
            for (int i = 0; i < 8; i++)
#pragma unroll
                for (int j = 0; j < 4; j++) sacc[i][j] = 0.f;

#pragma unroll
            for (int nbp = 0; nbp < 4; nbp++) {
#pragma unroll
                for (int ks = 0; ks < 4; ks++) {
                    uint32_t kd = st + (nbp * 16 + b_row) * AT_ROWB + ks * 32 + b_off;
                    uint32_t rh[4], rl[4];
                    ldsm4(rh[0], rh[1], rh[2], rh[3], kd);
                    ldsm4(rl[0], rl[1], rl[2], rl[3], kd + AK_T);
                    uint32_t b0h[2] = {rh[0], rh[1]}, b1h[2] = {rh[2], rh[3]};
                    uint32_t b0l[2] = {rl[0], rl[1]}, b1l[2] = {rl[2], rl[3]};
                    // interleave the two accumulators between split terms
                    MMA16816(sacc[2 * nbp],     qfh[ks], b0h);
                    MMA16816(sacc[2 * nbp + 1], qfh[ks], b1h);
                    MMA16816(sacc[2 * nbp],     qfl[ks], b0h);
                    MMA16816(sacc[2 * nbp + 1], qfl[ks], b1h);
                    MMA16816(sacc[2 * nbp],     qfh[ks], b0l);
                    MMA16816(sacc[2 * nbp + 1], qfh[ks], b1l);
                }
            }

            // ---- causal mask (only when tile crosses the diagonal) ----
            if (kt * 64 + 63 > q0 + wq) {
                const int qg0 = q0 + wq + gr, qg1 = qg0 + 8;
#pragma unroll
                for (int nb = 0; nb < 8; nb++) {
                    int kg = kt * 64 + nb * 8 + 2 * gc;
                    if (kg     > qg0) sacc[nb][0] = -1e30f;
                    if (kg + 1 > qg0) sacc[nb][1] = -1e30f;
                    if (kg     > qg1) sacc[nb][2] = -1e30f;
                    if (kg + 1 > qg1) sacc[nb][3] = -1e30f;
                }
            }

            // ---- online softmax ----
            float mx0 = m0, mx1 = m1;
#pragma unroll
            for (int nb = 0; nb < 8; nb++) {
                mx0 = fmaxf(mx0, fmaxf(sacc[nb][0], sacc[nb][1]));
                mx1 = fmaxf(mx1, fmaxf(sacc[nb][2], sacc[nb][3]));
            }
            mx0 = fmaxf(mx0, __shfl_xor_sync(0xffffffffu, mx0, 1));
            mx0 = fmaxf(mx0, __shfl_xor_sync(0xffffffffu, mx0, 2));
            mx1 = fmaxf(mx1, __shfl_xor_sync(0xffffffffu, mx1, 1));
            mx1 = fmaxf(mx1, __shfl_xor_sync(0xffffffffu, mx1, 2));
            float al0 = __expf(m0 - mx0), al1 = __expf(m1 - mx1);
            m0 = mx0; m1 = mx1;
            float ls0 = 0.f, ls1 = 0.f;
#pragma unroll
            for (int nb = 0; nb < 8; nb++) {
                sacc[nb][0] = __expf(sacc[nb][0] - mx0); ls0 += sacc[nb][0];
                sacc[nb][1] = __expf(sacc[nb][1] - mx0); ls0 += sacc[nb][1];
                sacc[nb][2] = __expf(sacc[nb][2] - mx1); ls1 += sacc[nb][2];
                sacc[nb][3] = __expf(sacc[nb][3] - mx1); ls1 += sacc[nb][3];
            }
            l0 = l0 * al0 + ls0;
            l1 = l1 * al1 + ls1;
#pragma unroll
            for (int nb = 0; nb < 8; nb++) {
                Oacc[nb][0] *= al0; Oacc[nb][1] *= al0;
                Oacc[nb][2] *= al1; Oacc[nb][3] *= al1;
            }

            // ---- O += P @ V (3-term split) ----
#pragma unroll
            for (int kb = 0; kb < 4; kb++) {
                uint32_t ph[4], pl[4];
                split_pack2(sacc[2 * kb][0],     sacc[2 * kb][1],     ph[0], pl[0]);
                split_pack2(sacc[2 * kb][2],     sacc[2 * kb][3],     ph[1], pl[1]);
                split_pack2(sacc[2 * kb + 1][0], sacc[2 * kb + 1][1], ph[2], pl[2]);
                split_pack2(sacc[2 * kb + 1][2], sacc[2 * kb + 1][3], ph[3], pl[3]);
#pragma unroll
                for (int nbp = 0; nbp < 4; nbp++) {
                    uint32_t vd = st + 2 * AK_T + (kb * 16 + v_row) * AT_ROWB + nbp * 32 + v_off;
                    uint32_t rh[4], rl[4];
                    ldsm4t(rh[0], rh[1], rh[2], rh[3], vd);
                    ldsm4t(rl[0], rl[1], rl[2], rl[3], vd + AK_T);
                    uint32_t v0h[2] = {rh[0], rh[1]}, v1h[2] = {rh[2], rh[3]};
                    uint32_t v0l[2] = {rl[0], rl[1]}, v1l[2] = {rl[2], rl[3]};
                    MMA16816(Oacc[2 * nbp],     ph, v0h);
                    MMA16816(Oacc[2 * nbp + 1], ph, v1h);
                    MMA16816(Oacc[2 * nbp],     pl, v0h);
                    MMA16816(Oacc[2 * nbp + 1], pl, v1h);
                    MMA16816(Oacc[2 * nbp],     ph, v0l);
                    MMA16816(Oacc[2 * nbp + 1], ph, v1l);
                }
            }
        }

        CP_WAIT0();
        __syncthreads();
    }

    // ---- finalize ----
    l0 += __shfl_xor_sync(0xffffffffu, l0, 1);
    l0 += __shfl_xor_sync(0xffffffffu, l0, 2);
    l1 += __shfl_xor_sync(0xffffffffu, l1, 1);
    l1 += __shfl_xor_sync(0xffffffffu, l1, 2);
    const float inv0 = 1.f / l0, inv1 = 1.f / l1;

    float* yb = y + ((size_t)b * T_ + q0 + wq) * C_ + h * D_;
#pragma unroll
    for (int nb = 0; nb < 8; nb++) {
        int col = nb * 8 + 2 * gc;
        *(float2*)(yb + (size_t)gr * C_ + col) =
            make_float2(Oacc[nb][0] * inv0, Oacc[nb][1] * inv0);
        *(float2*)(yb + (size_t)(gr + 8) * C_ + col) =
            make_float2(Oacc[nb][2] * inv1, Oacc[nb][3] * inv1);
    }
}

// ---------------- residual add + LayerNorm (+ optional split) --------------
template <bool SPLIT>
__global__ void __launch_bounds__(256) add_ln_kernel(
    const float* __restrict__ a, const float* __restrict__ bres,
    const float* __restrict__ g, const float* __restrict__ beta,
    float* __restrict__ out, __half* __restrict__ Oh,
    __half* __restrict__ Ol)
{
    const int row = blockIdx.x;
    const int tid = threadIdx.x;

    const float4 av = ((const float4*)(a    + (size_t)row * C_))[tid];
    const float4 bv = ((const float4*)(bres + (size_t)row * C_))[tid];
    float4 v = make_float4(av.x + bv.x, av.y + bv.y, av.z + bv.z, av.w + bv.w);

    float s  = v.x + v.y + v.z + v.w;
    float sq = v.x * v.x + v.y * v.y + v.z * v.z + v.w * v.w;
#pragma unroll
    for (int off = 16; off; off >>= 1) {
        s  += __shfl_xor_sync(0xffffffffu, s,  off);
        sq += __shfl_xor_sync(0xffffffffu, sq, off);
    }
    __shared__ float ws[8], wsq[8];
    if ((tid & 31) == 0) { ws[tid >> 5] = s; wsq[tid >> 5] = sq; }
    __syncthreads();
    float tot = 0.f, totq = 0.f;
#pragma unroll
    for (int i = 0; i < 8; i++) { tot += ws[i]; totq += wsq[i]; }

    const float mu   = tot * (1.0f / C_);
    const float var  = totq * (1.0f / C_) - mu * mu;
    const float rstd = rsqrtf(var + LN_EPS);

    const float4 gv = ((const float4*)g)[tid];
    const float4 be = ((const float4*)beta)[tid];
    float4 o;
    o.x = (v.x - mu) * rstd * gv.x + be.x;
    o.y = (v.y - mu) * rstd * gv.y + be.y;
    o.z = (v.z - mu) * rstd * gv.z + be.z;
    o.w = (v.w - mu) * rstd * gv.w + be.w;
    ((float4*)(out + (size_t)row * C_))[tid] = o;
    if (SPLIT) {
        uint32_t h0, l0v, h1, l1v;
        split_pack2(o.x, o.y, h0, l0v);
        split_pack2(o.z, o.w, h1, l1v);
        uint32_t* oh = (uint32_t*)(Oh + (size_t)row * C_);
        uint32_t* ol = (uint32_t*)(Ol + (size_t)row * C_);
        oh[2 * tid] = h0; oh[2 * tid + 1] = h1;
        ol[2 * tid] = l0v; ol[2 * tid + 1] = l1v;
    }
}

// ---------------- launcher --------------------------------------------------
extern "C" void kernel_launch(void* const* d_in, const int* in_sizes, int n_in,
                              void* d_out, int out_size)
{
    const float* x     = (const float*)d_in[0];
    const float* w_qkv = (const float*)d_in[1];
    const float* b_qkv = (const float*)d_in[2];
    const float* ln1_g = (const float*)d_in[3];
    const float* ln1_b = (const float*)d_in[4];
    const float* w_fc1 = (const float*)d_in[5];
    const float* b_fc1 = (const float*)d_in[6];
    const float* w_fc2 = (const float*)d_in[7];
    const float* b_fc2 = (const float*)d_in[8];
    const float* ln2_g = (const float*)d_in[9];
    const float* ln2_b = (const float*)d_in[10];
    float* out = (float*)d_out;

    float *att, *x1, *mlp;
    __half *qkvh, *qkvl, *ah, *al, *ah2, *al2, *bh;
    cudaGetSymbolAddress((void**)&att,  g_att);
    cudaGetSymbolAddress((void**)&x1,   g_x1);
    cudaGetSymbolAddress((void**)&mlp,  g_mlp);
    cudaGetSymbolAddress((void**)&qkvh, g_qkvh);
    cudaGetSymbolAddress((void**)&qkvl, g_qkvl);
    cudaGetSymbolAddress((void**)&ah,   g_ah);
    cudaGetSymbolAddress((void**)&al,   g_al);
    cudaGetSymbolAddress((void**)&ah2,  g_ah2);
    cudaGetSymbolAddress((void**)&al2,  g_al2);
    cudaGetSymbolAddress((void**)&bh,   g_bh);

    cudaFuncSetAttribute(gemm_mma<0>, cudaFuncAttributeMaxDynamicSharedMemorySize, GM_SMEM);
    cudaFuncSetAttribute(gemm_mma<1>, cudaFuncAttributeMaxDynamicSharedMemorySize, GM_SMEM);
    cudaFuncSetAttribute(gemm_mma<2>, cudaFuncAttributeMaxDynamicSharedMemorySize, GM_SMEM);
    cudaFuncSetAttribute(attn_tc, cudaFuncAttributeMaxDynamicSharedMemorySize, AT_SMEM);

    // ---- QKV = x @ w_qkv + b  -> split fp16 (Q scaled 1/8) ----
    split_act<<<(M_ * C_ / 4 + 255) / 256, 256>>>(x, ah, al, (size_t)M_ * C_ / 4);
    round_w_t<<<dim3(3 * C_ / 32, C_ / 32), dim3(32, 8)>>>(w_qkv, bh, C_, 3 * C_);
    gemm_mma<1><<<dim3(3 * C_ / 128, M_ / 256), 256, GM_SMEM>>>(
        ah, al, bh, b_qkv, nullptr, qkvh, qkvl, 3 * C_, C_);

    // ---- attention (tensor core, 128 q / CTA) ----
    attn_tc<<<dim3(T_ / 128, H_, B_), 256, AT_SMEM>>>(qkvh, qkvl, att);

    // ---- x1 = LN1(x + att), fused split for FC1 A ----
    add_ln_kernel<true><<<M_, 256>>>(x, att, ln1_g, ln1_b, x1, ah, al);

    // ---- h = gelu(x1 @ w_fc1 + b) -> split fp16 ----
    round_w_t<<<dim3(4 * C_ / 32, C_ / 32), dim3(32, 8)>>>(w_fc1, bh, C_, 4 * C_);
    gemm_mma<2><<<dim3(4 * C_ / 128, M_ / 256), 256, GM_SMEM>>>(
        ah, al, bh, b_fc1, nullptr, ah2, al2, 4 * C_, C_);

    // ---- mlp = h @ w_fc2 + b (fp32) ----
    round_w_t<<<dim3(C_ / 32, 4 * C_ / 32), dim3(32, 8)>>>(w_fc2, bh, 4 * C_, C_);
    gemm_mma<0><<<dim3(C_ / 128, M_ / 256), 256, GM_SMEM>>>(
        ah2, al2, bh, b_fc2, mlp, nullptr, nullptr, C_, 4 * C_);

    // ---- out = LN2(x1 + mlp) ----
    add_ln_kernel<false><<<M_, 256>>>(x1, mlp, ln2_g, ln2_b, out, nullptr, nullptr);
}

// round 9
// speedup vs baseline: 1.4490x; 1.4490x over previous
#include <cuda_runtime.h>
#include <cuda_fp16.h>
#include <math.h>
#include <stdint.h>

#define B_   4
#define T_   2048
#define C_   1024
#define H_   16
#define D_   64
#define M_   (B_ * T_)           // 8192 rows
#define LN_EPS 1e-5f

// ---------------- scratch (static device globals; no allocation) -----------
__device__ __align__(128) float g_att[(size_t)M_ * C_];
__device__ __align__(128) float g_x1 [(size_t)M_ * C_];
__device__ __align__(128) float g_mlp[(size_t)M_ * C_];
__device__ __align__(128) __half g_qkvh[(size_t)M_ * 3 * C_];
__device__ __align__(128) __half g_qkvl[(size_t)M_ * 3 * C_];
__device__ __align__(128) __half g_ah [(size_t)M_ * C_];       // A (x / x1) fp16
__device__ __align__(128) __half g_ah2[(size_t)M_ * 4 * C_];   // gelu(h) fp16
__device__ __align__(128) __half g_bh [(size_t)4 * C_ * C_];   // B [N,K] fp16

__device__ __forceinline__ float gelu_exact(float x) {
    return 0.5f * x * (1.0f + erff(x * 0.70710678118654752440f));
}

// ---------------- PTX helpers ----------------------------------------------
__device__ __forceinline__ uint32_t smem_u32(const void* p) {
    uint32_t a;
    asm("{ .reg .u64 t; cvta.to.shared.u64 t, %1; cvt.u32.u64 %0, t; }" : "=r"(a) : "l"(p));
    return a;
}
#define CP16(s, g) asm volatile("cp.async.cg.shared.global [%0], [%1], 16;" :: "r"(s), "l"(g))
#define CP_COMMIT() asm volatile("cp.async.commit_group;" ::: "memory")
#define CP_WAIT2()  asm volatile("cp.async.wait_group 2;" ::: "memory")
#define CP_WAIT0()  asm volatile("cp.async.wait_group 0;" ::: "memory")

__device__ __forceinline__ void ldsm4(uint32_t& r0, uint32_t& r1,
                                      uint32_t& r2, uint32_t& r3, uint32_t addr) {
    asm volatile("ldmatrix.sync.aligned.m8n8.x4.shared.b16 {%0,%1,%2,%3}, [%4];"
                 : "=r"(r0), "=r"(r1), "=r"(r2), "=r"(r3) : "r"(addr));
}
__device__ __forceinline__ void ldsm4t(uint32_t& r0, uint32_t& r1,
                                       uint32_t& r2, uint32_t& r3, uint32_t addr) {
    asm volatile("ldmatrix.sync.aligned.m8n8.x4.trans.shared.b16 {%0,%1,%2,%3}, [%4];"
                 : "=r"(r0), "=r"(r1), "=r"(r2), "=r"(r3) : "r"(addr));
}
#define MMA16816(c, a, b)                                                     \
    asm("mma.sync.aligned.m16n8k16.row.col.f32.f16.f16.f32 "                  \
        "{%0,%1,%2,%3}, {%4,%5,%6,%7}, {%8,%9}, {%0,%1,%2,%3};"               \
        : "+f"((c)[0]), "+f"((c)[1]), "+f"((c)[2]), "+f"((c)[3])              \
        : "r"((a)[0]), "r"((a)[1]), "r"((a)[2]), "r"((a)[3]),                 \
          "r"((b)[0]), "r"((b)[1]))

__device__ __forceinline__ uint32_t pack_f16x2(float lo, float hi) {
    uint32_t r;
    asm("cvt.rn.f16x2.f32 %0, %1, %2;" : "=r"(r) : "f"(hi), "f"(lo));
    return r;
}
// split (x,y) into hi f16x2 + residual-lo f16x2
__device__ __forceinline__ void split_pack2(float x, float y, uint32_t& hi, uint32_t& lo) {
    float hx = __half2float(__float2half_rn(x));
    float hy = __half2float(__float2half_rn(y));
    hi = pack_f16x2(hx, hy);
    lo = pack_f16x2(x - hx, y - hy);
}

// ---------------- conversion kernels ----------------------------------------
__global__ void __launch_bounds__(256) round_act(
    const float* __restrict__ X, __half* __restrict__ Hh, size_t n4)
{
    size_t i = (size_t)blockIdx.x * blockDim.x + threadIdx.x;
    if (i >= n4) return;
    float4 v = ((const float4*)X)[i];
    ((uint32_t*)Hh)[2 * i]     = pack_f16x2(v.x, v.y);
    ((uint32_t*)Hh)[2 * i + 1] = pack_f16x2(v.z, v.w);
}

// W [K,N] fp32 -> Bh [N,K] fp16 (transpose + single rounding)
__global__ void __launch_bounds__(256) round_w_t(
    const float* __restrict__ W, __half* __restrict__ Bh, int K, int N)
{
    __shared__ float t[32][33];
    const int tx = threadIdx.x, ty = threadIdx.y;   // block (32,8)
    const int n0 = blockIdx.x * 32, k0 = blockIdx.y * 32;
#pragma unroll
    for (int r = 0; r < 4; r++)
        t[ty + r * 8][tx] = W[(size_t)(k0 + ty + r * 8) * N + n0 + tx];
    __syncthreads();
#pragma unroll
    for (int r = 0; r < 4; r++) {
        int nn = ty + r * 8;
        Bh[(size_t)(n0 + nn) * K + k0 + tx] = __float2half_rn(t[tx][nn]);
    }
}

// ---------------- HMMA fp16 GEMM --------------------------------------------
// C = A@B^T + bias  (A, B single-rounded fp16, fp32 accum)
// CTA tile 256x128, warp tile 64x64 (8 warps = 4m x 2n), BK=32, 4 stages.
// MODE 0: fp32 out; MODE 1: split fp16 out, cols<C_ scaled 0.125 (QKV);
// MODE 2: gelu then fp16 out.
#define GM_BK     32
#define GM_ROWB   80
#define GM_AOP    (256 * GM_ROWB)             // 20480
#define GM_BOP    (128 * GM_ROWB)             // 10240
#define GM_STAGE  (GM_AOP + GM_BOP)           // 30720
#define GM_SMEM   (4 * GM_STAGE)              // 122880

template <int MODE>
__global__ void __launch_bounds__(256, 1) gemm_mma(
    const __half* __restrict__ Ah, const __half* __restrict__ Bh,
    const float* __restrict__ bias, float* __restrict__ Cmat,
    __half* __restrict__ Oh, __half* __restrict__ Ol,
    int N, int K)
{
    extern __shared__ char smem[];
    const uint32_t sb = smem_u32(smem);
    const int tid  = threadIdx.x;
    const int lane = tid & 31;
    const int wid  = tid >> 5;
    const int m0 = blockIdx.y * 256;
    const int n0 = blockIdx.x * 128;
    const int wm = (wid >> 1) * 64;
    const int wn = (wid & 1) * 64;

    const int nch = K / GM_BK;

    auto load_chunk = [&](int c) {
        const int kk = c * GM_BK;
        const uint32_t st = sb + (c & 3) * GM_STAGE;
#pragma unroll
        for (int i = 0; i < 4; i++) {                // A: 1024 x 16B units
            int u = tid + i * 256;
            int r = u >> 2, cc = u & 3;
            CP16(st + r * GM_ROWB + cc * 16, Ah + (size_t)(m0 + r) * K + kk + cc * 8);
        }
#pragma unroll
        for (int i = 0; i < 2; i++) {                // B: 512 x 16B units
            int u = tid + i * 256;
            int r = u >> 2, cc = u & 3;
            CP16(st + GM_AOP + r * GM_ROWB + cc * 16, Bh + (size_t)(n0 + r) * K + kk + cc * 8);
        }
    };

    float acc[4][8][4];
#pragma unroll
    for (int i = 0; i < 4; i++)
#pragma unroll
        for (int j = 0; j < 8; j++)
#pragma unroll
            for (int t = 0; t < 4; t++) acc[i][j][t] = 0.f;

    load_chunk(0); CP_COMMIT();
    load_chunk(1); CP_COMMIT();
    load_chunk(2); CP_COMMIT();

    const int a_row = lane & 15;
    const int a_off = (lane >> 4) * 16;
    const int b_row = (lane & 7) + ((lane >> 4) << 3);
    const int b_off = ((lane >> 3) & 1) * 16;

    for (int k = 0; k < nch; k++) {
        CP_WAIT2();                       // 3 groups pending -> chunk k resident
        __syncthreads();
        if (k + 3 < nch) load_chunk(k + 3);
        CP_COMMIT();                      // unconditional: keeps pending-count invariant

        const uint32_t stA = sb + (k & 3) * GM_STAGE;
        const uint32_t stB = stA + GM_AOP;

#pragma unroll
        for (int ks = 0; ks < 2; ks++) {
            uint32_t ah[4][4];
#pragma unroll
            for (int mb = 0; mb < 4; mb++) {
                uint32_t ad = stA + (wm + mb * 16 + a_row) * GM_ROWB + ks * 32 + a_off;
                ldsm4(ah[mb][0], ah[mb][1], ah[mb][2], ah[mb][3], ad);
            }
#pragma unroll
            for (int nbp = 0; nbp < 4; nbp++) {
                uint32_t bd = stB + (wn + nbp * 16 + b_row) * GM_ROWB + ks * 32 + b_off;
                uint32_t h0, h1, h2, h3;
                ldsm4(h0, h1, h2, h3, bd);
                uint32_t b0h[2] = {h0, h1}, b1h[2] = {h2, h3};
#pragma unroll
                for (int mb = 0; mb < 4; mb++) MMA16816(acc[mb][2 * nbp],     ah[mb], b0h);
#pragma unroll
                for (int mb = 0; mb < 4; mb++) MMA16816(acc[mb][2 * nbp + 1], ah[mb], b1h);
            }
        }
    }

    // ---- epilogue ----
    const int gr = lane >> 2;
    const int gc = (lane & 3) * 2;
#pragma unroll
    for (int mb = 0; mb < 4; mb++) {
#pragma unroll
        for (int nb = 0; nb < 8; nb++) {
            int row = m0 + wm + mb * 16 + gr;
            int col = n0 + wn + nb * 8 + gc;
            float b0 = __ldg(&bias[col]), b1 = __ldg(&bias[col + 1]);
            float v0 = acc[mb][nb][0] + b0, v1 = acc[mb][nb][1] + b1;
            float v2 = acc[mb][nb][2] + b0, v3 = acc[mb][nb][3] + b1;
            if (MODE == 0) {
                *(float2*)(Cmat + (size_t)row * N + col)       = make_float2(v0, v1);
                *(float2*)(Cmat + (size_t)(row + 8) * N + col) = make_float2(v2, v3);
            } else if (MODE == 1) {
                if (col < C_) { v0 *= 0.125f; v1 *= 0.125f; v2 *= 0.125f; v3 *= 0.125f; }
                uint32_t h01, l01, h23, l23;
                split_pack2(v0, v1, h01, l01);
                split_pack2(v2, v3, h23, l23);
                *(uint32_t*)(Oh + (size_t)row * N + col)       = h01;
                *(uint32_t*)(Ol + (size_t)row * N + col)       = l01;
                *(uint32_t*)(Oh + (size_t)(row + 8) * N + col) = h23;
                *(uint32_t*)(Ol + (size_t)(row + 8) * N + col) = l23;
            } else {  // MODE 2: gelu -> fp16
                v0 = gelu_exact(v0); v1 = gelu_exact(v1);
                v2 = gelu_exact(v2); v3 = gelu_exact(v3);
                *(uint32_t*)(Oh + (size_t)row * N + col)       = pack_f16x2(v0, v1);
                *(uint32_t*)(Oh + (size_t)(row + 8) * N + col) = pack_f16x2(v2, v3);
            }
        }
    }
}

// ---------------- tensor-core causal flash attention ------------------------
// 128 queries per CTA (8 warps x 16 rows), 64-key tiles, 3-term fp16 MMAs.
#define AT_ROWB  144
#define AQ_T     (128 * AT_ROWB)             // 18432 per Q operand
#define AK_T     (64 * AT_ROWB)              // 9216 per K/V operand
#define AT_STAGE (4 * AK_T)                  // Kh,Kl,Vh,Vl = 36864
#define AT_SMEM  (2 * AQ_T + 2 * AT_STAGE)   // 110592

__global__ void __launch_bounds__(256, 1) attn_tc(
    const __half* __restrict__ qkvh,
    const __half* __restrict__ qkvl,
    float* __restrict__ y)
{
    extern __shared__ char smem[];
    const uint32_t sb = smem_u32(smem);
    const int tid = threadIdx.x, lane = tid & 31, wid = tid >> 5;
    const int qb = (int)gridDim.x - 1 - (int)blockIdx.x;   // big blocks first
    const int h = blockIdx.y, b = blockIdx.z;
    const int q0 = qb * 128;
    const int wq = wid * 16;
    const int gr = lane >> 2, gc = lane & 3;
    const int RS = 3 * C_;

    const __half* qh = qkvh + (size_t)b * T_ * RS + h * D_;
    const __half* ql = qkvl + (size_t)b * T_ * RS + h * D_;
    const __half* kh = qh + C_;
    const __half* kl = ql + C_;
    const __half* vh = qh + 2 * C_;
    const __half* vl = ql + 2 * C_;

    const uint32_t QH  = sb;
    const uint32_t ST0 = sb + 2 * AQ_T;

    // load Q (hi/lo) tile: 128 rows x 128B each
#pragma unroll
    for (int t = 0; t < 2; t++) {
        const __half* g = t ? ql : qh;
#pragma unroll
        for (int i = 0; i < 4; i++) {
            int u = tid + i * 256;          // 0..1023
            int r = u >> 3, c = u & 7;
            CP16(QH + t * AQ_T + r * AT_ROWB + c * 16, g + (size_t)(q0 + r) * RS + c * 8);
        }
    }

    auto load_tile = [&](int kt, int bufsel) {
        uint32_t st = ST0 + bufsel * AT_STAGE;
#pragma unroll
        for (int t = 0; t < 4; t++) {
            const __half* g = (t == 0 ? kh : t == 1 ? kl : t == 2 ? vh : vl);
#pragma unroll
            for (int i = 0; i < 2; i++) {
                int u = tid + i * 256;      // 0..511
                int r = u >> 3, c = u & 7;
                CP16(st + t * AK_T + r * AT_ROWB + c * 16, g + (size_t)(kt * 64 + r) * RS + c * 8);
            }
        }
    };
    load_tile(0, 0);
    CP_COMMIT();
    CP_WAIT0();
    __syncthreads();

    // Q fragments
    uint32_t qfh[4][4], qfl[4][4];
    const int a_row = lane & 15, a_off = (lane >> 4) * 16;
#pragma unroll
    for (int ks = 0; ks < 4; ks++) {
        uint32_t ad = QH + (wq + a_row) * AT_ROWB + ks * 32 + a_off;
        ldsm4(qfh[ks][0], qfh[ks][1], qfh[ks][2], qfh[ks][3], ad);
        ldsm4(qfl[ks][0], qfl[ks][1], qfl[ks][2], qfl[ks][3], ad + AQ_T);
    }

    float Oacc[8][4];
#pragma unroll
    for (int i = 0; i < 8; i++)
#pragma unroll
        for (int j = 0; j < 4; j++) Oacc[i][j] = 0.f;
    float m0 = -1e30f, m1 = -1e30f, l0 = 0.f, l1 = 0.f;

    const int nt = 2 * qb + 2;
    const int b_row = (lane & 7) + ((lane >> 4) << 3);
    const int b_off = ((lane >> 3) & 1) * 16;
    const int v_row = (lane & 7) + ((lane >> 3) & 1) * 8;
    const int v_off = (lane >> 4) * 16;

    for (int kt = 0; kt < nt; kt++) {
        if (kt + 1 < nt) { load_tile(kt + 1, (kt + 1) & 1); CP_COMMIT(); }
        const uint32_t st = ST0 + (kt & 1) * AT_STAGE;

        // warp-level skip: keys all strictly above this warp's queries
        const bool active = (kt * 64) <= (q0 + wq + 15);
        if (active) {
            // ---- S = Q @ K^T (3-term split) ----
            float sacc[8][4];
#pragma unroll
            for (int i = 0; i < 8; i++)
#pragma unroll
                for (int j = 0; j < 4; j++) sacc[i][j] = 0.f;

#pragma unroll
            for (int nbp = 0; nbp < 4; nbp++) {
#pragma unroll
                for (int ks = 0; ks < 4; ks++) {
                    uint32_t kd = st + (nbp * 16 + b_row) * AT_ROWB + ks * 32 + b_off;
                    uint32_t rh[4], rl[4];
                    ldsm4(rh[0], rh[1], rh[2], rh[3], kd);
                    ldsm4(rl[0], rl[1], rl[2], rl[3], kd + AK_T);
                    uint32_t b0h[2] = {rh[0], rh[1]}, b1h[2] = {rh[2], rh[3]};
                    uint32_t b0l[2] = {rl[0], rl[1]}, b1l[2] = {rl[2], rl[3]};
                    MMA16816(sacc[2 * nbp],     qfh[ks], b0h);
                    MMA16816(sacc[2 * nbp + 1], qfh[ks], b1h);
                    MMA16816(sacc[2 * nbp],     qfl[ks], b0h);
                    MMA16816(sacc[2 * nbp + 1], qfl[ks], b1h);
                    MMA16816(sacc[2 * nbp],     qfh[ks], b0l);
                    MMA16816(sacc[2 * nbp + 1], qfh[ks], b1l);
                }
            }

            // ---- causal mask (only when tile crosses the diagonal) ----
            if (kt * 64 + 63 > q0 + wq) {
                const int qg0 = q0 + wq + gr, qg1 = qg0 + 8;
#pragma unroll
                for (int nb = 0; nb < 8; nb++) {
                    int kg = kt * 64 + nb * 8 + 2 * gc;
                    if (kg     > qg0) sacc[nb][0] = -1e30f;
                    if (kg + 1 > qg0) sacc[nb][1] = -1e30f;
                    if (kg     > qg1) sacc[nb][2] = -1e30f;
                    if (kg + 1 > qg1) sacc[nb][3] = -1e30f;
                }
            }

            // ---- online softmax ----
            float mx0 = m0, mx1 = m1;
#pragma unroll
            for (int nb = 0; nb < 8; nb++) {
                mx0 = fmaxf(mx0, fmaxf(sacc[nb][0], sacc[nb][1]));
                mx1 = fmaxf(mx1, fmaxf(sacc[nb][2], sacc[nb][3]));
            }
            mx0 = fmaxf(mx0, __shfl_xor_sync(0xffffffffu, mx0, 1));
            mx0 = fmaxf(mx0, __shfl_xor_sync(0xffffffffu, mx0, 2));
            mx1 = fmaxf(mx1, __shfl_xor_sync(0xffffffffu, mx1, 1));
            mx1 = fmaxf(mx1, __shfl_xor_sync(0xffffffffu, mx1, 2));
            float al0 = __expf(m0 - mx0), al1 = __expf(m1 - mx1);
            m0 = mx0; m1 = mx1;
            float ls0 = 0.f, ls1 = 0.f;
#pragma unroll
            for (int nb = 0; nb < 8; nb++) {
                sacc[nb][0] = __expf(sacc[nb][0] - mx0); ls0 += sacc[nb][0];
                sacc[nb][1] = __expf(sacc[nb][1] - mx0); ls0 += sacc[nb][1];
                sacc[nb][2] = __expf(sacc[nb][2] - mx1); ls1 += sacc[nb][2];
                sacc[nb][3] = __expf(sacc[nb][3] - mx1); ls1 += sacc[nb][3];
            }
            l0 = l0 * al0 + ls0;
            l1 = l1 * al1 + ls1;
#pragma unroll
            for (int nb = 0; nb < 8; nb++) {
                Oacc[nb][0] *= al0; Oacc[nb][1] *= al0;
                Oacc[nb][2] *= al1; Oacc[nb][3] *= al1;
            }

            // ---- O += P @ V (3-term split) ----
#pragma unroll
            for (int kb = 0; kb < 4; kb++) {
                uint32_t ph[4], pl[4];
                split_pack2(sacc[2 * kb][0],     sacc[2 * kb][1],     ph[0], pl[0]);
                split_pack2(sacc[2 * kb][2],     sacc[2 * kb][3],     ph[1], pl[1]);
                split_pack2(sacc[2 * kb + 1][0], sacc[2 * kb + 1][1], ph[2], pl[2]);
                split_pack2(sacc[2 * kb + 1][2], sacc[2 * kb + 1][3], ph[3], pl[3]);
#pragma unroll
                for (int nbp = 0; nbp < 4; nbp++) {
                    uint32_t vd = st + 2 * AK_T + (kb * 16 + v_row) * AT_ROWB + nbp * 32 + v_off;
                    uint32_t rh[4], rl[4];
                    ldsm4t(rh[0], rh[1], rh[2], rh[3], vd);
                    ldsm4t(rl[0], rl[1], rl[2], rl[3], vd + AK_T);
                    uint32_t v0h[2] = {rh[0], rh[1]}, v1h[2] = {rh[2], rh[3]};
                    uint32_t v0l[2] = {rl[0], rl[1]}, v1l[2] = {rl[2], rl[3]};
                    MMA16816(Oacc[2 * nbp],     ph, v0h);
                    MMA16816(Oacc[2 * nbp + 1], ph, v1h);
                    MMA16816(Oacc[2 * nbp],     pl, v0h);
                    MMA16816(Oacc[2 * nbp + 1], pl, v1h);
                    MMA16816(Oacc[2 * nbp],     ph, v0l);
                    MMA16816(Oacc[2 * nbp + 1], ph, v1l);
                }
            }
        }

        CP_WAIT0();
        __syncthreads();
    }

    // ---- finalize ----
    l0 += __shfl_xor_sync(0xffffffffu, l0, 1);
    l0 += __shfl_xor_sync(0xffffffffu, l0, 2);
    l1 += __shfl_xor_sync(0xffffffffu, l1, 1);
    l1 += __shfl_xor_sync(0xffffffffu, l1, 2);
    const float inv0 = 1.f / l0, inv1 = 1.f / l1;

    float* yb = y + ((size_t)b * T_ + q0 + wq) * C_ + h * D_;
#pragma unroll
    for (int nb = 0; nb < 8; nb++) {
        int col = nb * 8 + 2 * gc;
        *(float2*)(yb + (size_t)gr * C_ + col) =
            make_float2(Oacc[nb][0] * inv0, Oacc[nb][1] * inv0);
        *(float2*)(yb + (size_t)(gr + 8) * C_ + col) =
            make_float2(Oacc[nb][2] * inv1, Oacc[nb][3] * inv1);
    }
}

// ---------------- residual add + LayerNorm (+ optional fp16 out) -----------
template <bool SPLIT>
__global__ void __launch_bounds__(256) add_ln_kernel(
    const float* __restrict__ a, const float* __restrict__ bres,
    const float* __restrict__ g, const float* __restrict__ beta,
    float* __restrict__ out, __half* __restrict__ Oh)
{
    const int row = blockIdx.x;
    const int tid = threadIdx.x;

    const float4 av = ((const float4*)(a    + (size_t)row * C_))[tid];
    const float4 bv = ((const float4*)(bres + (size_t)row * C_))[tid];
    float4 v = make_float4(av.x + bv.x, av.y + bv.y, av.z + bv.z, av.w + bv.w);

    float s  = v.x + v.y + v.z + v.w;
    float sq = v.x * v.x + v.y * v.y + v.z * v.z + v.w * v.w;
#pragma unroll
    for (int off = 16; off; off >>= 1) {
        s  += __shfl_xor_sync(0xffffffffu, s,  off);
        sq += __shfl_xor_sync(0xffffffffu, sq, off);
    }
    __shared__ float ws[8], wsq[8];
    if ((tid & 31) == 0) { ws[tid >> 5] = s; wsq[tid >> 5] = sq; }
    __syncthreads();
    float tot = 0.f, totq = 0.f;
#pragma unroll
    for (int i = 0; i < 8; i++) { tot += ws[i]; totq += wsq[i]; }

    const float mu   = tot * (1.0f / C_);
    const float var  = totq * (1.0f / C_) - mu * mu;
    const float rstd = rsqrtf(var + LN_EPS);

    const float4 gv = ((const float4*)g)[tid];
    const float4 be = ((const float4*)beta)[tid];
    float4 o;
    o.x = (v.x - mu) * rstd * gv.x + be.x;
    o.y = (v.y - mu) * rstd * gv.y + be.y;
    o.z = (v.z - mu) * rstd * gv.z + be.z;
    o.w = (v.w - mu) * rstd * gv.w + be.w;
    ((float4*)(out + (size_t)row * C_))[tid] = o;
    if (SPLIT) {
        uint32_t* oh = (uint32_t*)(Oh + (size_t)row * C_);
        oh[2 * tid]     = pack_f16x2(o.x, o.y);
        oh[2 * tid + 1] = pack_f16x2(o.z, o.w);
    }
}

// ---------------- launcher --------------------------------------------------
extern "C" void kernel_launch(void* const* d_in, const int* in_sizes, int n_in,
                              void* d_out, int out_size)
{
    const float* x     = (const float*)d_in[0];
    const float* w_qkv = (const float*)d_in[1];
    const float* b_qkv = (const float*)d_in[2];
    const float* ln1_g = (const float*)d_in[3];
    const float* ln1_b = (const float*)d_in[4];
    const float* w_fc1 = (const float*)d_in[5];
    const float* b_fc1 = (const float*)d_in[6];
    const float* w_fc2 = (const float*)d_in[7];
    const float* b_fc2 = (const float*)d_in[8];
    const float* ln2_g = (const float*)d_in[9];
    const float* ln2_b = (const float*)d_in[10];
    float* out = (float*)d_out;

    float *att, *x1, *mlp;
    __half *qkvh, *qkvl, *ah, *ah2, *bh;
    cudaGetSymbolAddress((void**)&att,  g_att);
    cudaGetSymbolAddress((void**)&x1,   g_x1);
    cudaGetSymbolAddress((void**)&mlp,  g_mlp);
    cudaGetSymbolAddress((void**)&qkvh, g_qkvh);
    cudaGetSymbolAddress((void**)&qkvl, g_qkvl);
    cudaGetSymbolAddress((void**)&ah,   g_ah);
    cudaGetSymbolAddress((void**)&ah2,  g_ah2);
    cudaGetSymbolAddress((void**)&bh,   g_bh);

    cudaFuncSetAttribute(gemm_mma<0>, cudaFuncAttributeMaxDynamicSharedMemorySize, GM_SMEM);
    cudaFuncSetAttribute(gemm_mma<1>, cudaFuncAttributeMaxDynamicSharedMemorySize, GM_SMEM);
    cudaFuncSetAttribute(gemm_mma<2>, cudaFuncAttributeMaxDynamicSharedMemorySize, GM_SMEM);
    cudaFuncSetAttribute(attn_tc, cudaFuncAttributeMaxDynamicSharedMemorySize, AT_SMEM);

    // ---- QKV = x @ w_qkv + b  -> split fp16 (Q scaled 1/8) ----
    round_act<<<(M_ * C_ / 4 + 255) / 256, 256>>>(x, ah, (size_t)M_ * C_ / 4);
    round_w_t<<<dim3(3 * C_ / 32, C_ / 32), dim3(32, 8)>>>(w_qkv, bh, C_, 3 * C_);
    gemm_mma<1><<<dim3(3 * C_ / 128, M_ / 256), 256, GM_SMEM>>>(
        ah, bh, b_qkv, nullptr, qkvh, qkvl, 3 * C_, C_);

    // ---- attention (tensor core, 128 q / CTA) ----
    attn_tc<<<dim3(T_ / 128, H_, B_), 256, AT_SMEM>>>(qkvh, qkvl, att);

    // ---- x1 = LN1(x + att), fused fp16 round for FC1 A ----
    add_ln_kernel<true><<<M_, 256>>>(x, att, ln1_g, ln1_b, x1, ah);

    // ---- h = gelu(x1 @ w_fc1 + b) -> fp16 ----
    round_w_t<<<dim3(4 * C_ / 32, C_ / 32), dim3(32, 8)>>>(w_fc1, bh, C_, 4 * C_);
    gemm_mma<2><<<dim3(4 * C_ / 128, M_ / 256), 256, GM_SMEM>>>(
        ah, bh, b_fc1, nullptr, ah2, nullptr, 4 * C_, C_);

    // ---- mlp = h @ w_fc2 + b (fp32) ----
    round_w_t<<<dim3(C_ / 32, 4 * C_ / 32), dim3(32, 8)>>>(w_fc2, bh, 4 * C_, C_);
    gemm_mma<0><<<dim3(C_ / 128, M_ / 256), 256, GM_SMEM>>>(
        ah2, bh, b_fc2, mlp, nullptr, nullptr, C_, 4 * C_);

    // ---- out = LN2(x1 + mlp) ----
    add_ln_kernel<false><<<M_, 256>>>(x1, mlp, ln2_g, ln2_b, out, nullptr);
}

// round 10
// speedup vs baseline: 1.5918x; 1.0986x over previous
#include <cuda_runtime.h>
#include <cuda_fp16.h>
#include <math.h>
#include <stdint.h>

#define B_   4
#define T_   2048
#define C_   1024
#define H_   16
#define D_   64
#define M_   (B_ * T_)           // 8192 rows
#define LN_EPS 1e-5f

// ---------------- scratch (static device globals; no allocation) -----------
__device__ __align__(128) float g_att[(size_t)M_ * C_];
__device__ __align__(128) float g_x1 [(size_t)M_ * C_];
__device__ __align__(128) float g_mlp[(size_t)M_ * C_];
__device__ __align__(128) __half g_qkvh[(size_t)M_ * 3 * C_];
__device__ __align__(128) __half g_qkvl[(size_t)M_ * 3 * C_];   // lo used for Q,K only
__device__ __align__(128) __half g_ah [(size_t)M_ * C_];        // A (x / x1) fp16
__device__ __align__(128) __half g_ah2[(size_t)M_ * 4 * C_];    // gelu(h) fp16
__device__ __align__(128) __half g_bh [(size_t)4 * C_ * C_];    // B [N,K] fp16

__device__ __forceinline__ float gelu_exact(float x) {
    return 0.5f * x * (1.0f + erff(x * 0.70710678118654752440f));
}

// ---------------- PTX helpers ----------------------------------------------
__device__ __forceinline__ uint32_t smem_u32(const void* p) {
    uint32_t a;
    asm("{ .reg .u64 t; cvta.to.shared.u64 t, %1; cvt.u32.u64 %0, t; }" : "=r"(a) : "l"(p));
    return a;
}
#define CP16(s, g) asm volatile("cp.async.cg.shared.global [%0], [%1], 16;" :: "r"(s), "l"(g))
#define CP_COMMIT() asm volatile("cp.async.commit_group;" ::: "memory")
#define CP_WAIT2()  asm volatile("cp.async.wait_group 2;" ::: "memory")
#define CP_WAIT0()  asm volatile("cp.async.wait_group 0;" ::: "memory")

__device__ __forceinline__ void ldsm4(uint32_t& r0, uint32_t& r1,
                                      uint32_t& r2, uint32_t& r3, uint32_t addr) {
    asm volatile("ldmatrix.sync.aligned.m8n8.x4.shared.b16 {%0,%1,%2,%3}, [%4];"
                 : "=r"(r0), "=r"(r1), "=r"(r2), "=r"(r3) : "r"(addr));
}
__device__ __forceinline__ void ldsm4t(uint32_t& r0, uint32_t& r1,
                                       uint32_t& r2, uint32_t& r3, uint32_t addr) {
    asm volatile("ldmatrix.sync.aligned.m8n8.x4.trans.shared.b16 {%0,%1,%2,%3}, [%4];"
                 : "=r"(r0), "=r"(r1), "=r"(r2), "=r"(r3) : "r"(addr));
}
#define MMA16816(c, a, b)                                                     \
    asm("mma.sync.aligned.m16n8k16.row.col.f32.f16.f16.f32 "                  \
        "{%0,%1,%2,%3}, {%4,%5,%6,%7}, {%8,%9}, {%0,%1,%2,%3};"               \
        : "+f"((c)[0]), "+f"((c)[1]), "+f"((c)[2]), "+f"((c)[3])              \
        : "r"((a)[0]), "r"((a)[1]), "r"((a)[2]), "r"((a)[3]),                 \
          "r"((b)[0]), "r"((b)[1]))

__device__ __forceinline__ uint32_t pack_f16x2(float lo, float hi) {
    uint32_t r;
    asm("cvt.rn.f16x2.f32 %0, %1, %2;" : "=r"(r) : "f"(hi), "f"(lo));
    return r;
}
// split (x,y) into hi f16x2 + residual-lo f16x2
__device__ __forceinline__ void split_pack2(float x, float y, uint32_t& hi, uint32_t& lo) {
    float hx = __half2float(__float2half_rn(x));
    float hy = __half2float(__float2half_rn(y));
    hi = pack_f16x2(hx, hy);
    lo = pack_f16x2(x - hx, y - hy);
}

// ---------------- conversion kernels ----------------------------------------
__global__ void __launch_bounds__(256) round_act(
    const float* __restrict__ X, __half* __restrict__ Hh, size_t n4)
{
    size_t i = (size_t)blockIdx.x * blockDim.x + threadIdx.x;
    if (i >= n4) return;
    float4 v = ((const float4*)X)[i];
    ((uint32_t*)Hh)[2 * i]     = pack_f16x2(v.x, v.y);
    ((uint32_t*)Hh)[2 * i + 1] = pack_f16x2(v.z, v.w);
}

// W [K,N] fp32 -> Bh [N,K] fp16 (transpose + single rounding)
__global__ void __launch_bounds__(256) round_w_t(
    const float* __restrict__ W, __half* __restrict__ Bh, int K, int N)
{
    __shared__ float t[32][33];
    const int tx = threadIdx.x, ty = threadIdx.y;   // block (32,8)
    const int n0 = blockIdx.x * 32, k0 = blockIdx.y * 32;
#pragma unroll
    for (int r = 0; r < 4; r++)
        t[ty + r * 8][tx] = W[(size_t)(k0 + ty + r * 8) * N + n0 + tx];
    __syncthreads();
#pragma unroll
    for (int r = 0; r < 4; r++) {
        int nn = ty + r * 8;
        Bh[(size_t)(n0 + nn) * K + k0 + tx] = __float2half_rn(t[tx][nn]);
    }
}

// ---------------- HMMA fp16 GEMM --------------------------------------------
// C = A@B^T + bias  (A, B single-rounded fp16, fp32 accum)
// CTA tile 256x128, warp tile 64x64 (8 warps = 4m x 2n), BK=32, 4 stages.
// MODE 0: fp32 out; MODE 1: QKV out — Q cols scaled 0.125, hi always, lo only
//         for Q/K cols (< 2C); MODE 2: gelu then fp16 out.
#define GM_BK     32
#define GM_ROWB   80
#define GM_AOP    (256 * GM_ROWB)             // 20480
#define GM_BOP    (128 * GM_ROWB)             // 10240
#define GM_STAGE  (GM_AOP + GM_BOP)           // 30720
#define GM_SMEM   (4 * GM_STAGE)              // 122880

template <int MODE>
__global__ void __launch_bounds__(256, 1) gemm_mma(
    const __half* __restrict__ Ah, const __half* __restrict__ Bh,
    const float* __restrict__ bias, float* __restrict__ Cmat,
    __half* __restrict__ Oh, __half* __restrict__ Ol,
    int N, int K)
{
    extern __shared__ char smem[];
    const uint32_t sb = smem_u32(smem);
    const int tid  = threadIdx.x;
    const int lane = tid & 31;
    const int wid  = tid >> 5;
    const int m0 = blockIdx.y * 256;
    const int n0 = blockIdx.x * 128;
    const int wm = (wid >> 1) * 64;
    const int wn = (wid & 1) * 64;

    const int nch = K / GM_BK;

    auto load_chunk = [&](int c) {
        const int kk = c * GM_BK;
        const uint32_t st = sb + (c & 3) * GM_STAGE;
#pragma unroll
        for (int i = 0; i < 4; i++) {                // A: 1024 x 16B units
            int u = tid + i * 256;
            int r = u >> 2, cc = u & 3;
            CP16(st + r * GM_ROWB + cc * 16, Ah + (size_t)(m0 + r) * K + kk + cc * 8);
        }
#pragma unroll
        for (int i = 0; i < 2; i++) {                // B: 512 x 16B units
            int u = tid + i * 256;
            int r = u >> 2, cc = u & 3;
            CP16(st + GM_AOP + r * GM_ROWB + cc * 16, Bh + (size_t)(n0 + r) * K + kk + cc * 8);
        }
    };

    float acc[4][8][4];
#pragma unroll
    for (int i = 0; i < 4; i++)
#pragma unroll
        for (int j = 0; j < 8; j++)
#pragma unroll
            for (int t = 0; t < 4; t++) acc[i][j][t] = 0.f;

    load_chunk(0); CP_COMMIT();
    load_chunk(1); CP_COMMIT();
    load_chunk(2); CP_COMMIT();

    const int a_row = lane & 15;
    const int a_off = (lane >> 4) * 16;
    const int b_row = (lane & 7) + ((lane >> 4) << 3);
    const int b_off = ((lane >> 3) & 1) * 16;

    for (int k = 0; k < nch; k++) {
        CP_WAIT2();                       // 3 groups pending -> chunk k resident
        __syncthreads();
        if (k + 3 < nch) load_chunk(k + 3);
        CP_COMMIT();                      // unconditional: keeps pending-count invariant

        const uint32_t stA = sb + (k & 3) * GM_STAGE;
        const uint32_t stB = stA + GM_AOP;

#pragma unroll
        for (int ks = 0; ks < 2; ks++) {
            uint32_t ah[4][4];
#pragma unroll
            for (int mb = 0; mb < 4; mb++) {
                uint32_t ad = stA + (wm + mb * 16 + a_row) * GM_ROWB + ks * 32 + a_off;
                ldsm4(ah[mb][0], ah[mb][1], ah[mb][2], ah[mb][3], ad);
            }
#pragma unroll
            for (int nbp = 0; nbp < 4; nbp++) {
                uint32_t bd = stB + (wn + nbp * 16 + b_row) * GM_ROWB + ks * 32 + b_off;
                uint32_t h0, h1, h2, h3;
                ldsm4(h0, h1, h2, h3, bd);
                uint32_t b0h[2] = {h0, h1}, b1h[2] = {h2, h3};
#pragma unroll
                for (int mb = 0; mb < 4; mb++) MMA16816(acc[mb][2 * nbp],     ah[mb], b0h);
#pragma unroll
                for (int mb = 0; mb < 4; mb++) MMA16816(acc[mb][2 * nbp + 1], ah[mb], b1h);
            }
        }
    }

    // ---- epilogue ----
    const int gr = lane >> 2;
    const int gc = (lane & 3) * 2;
#pragma unroll
    for (int mb = 0; mb < 4; mb++) {
#pragma unroll
        for (int nb = 0; nb < 8; nb++) {
            int row = m0 + wm + mb * 16 + gr;
            int col = n0 + wn + nb * 8 + gc;
            float b0 = __ldg(&bias[col]), b1 = __ldg(&bias[col + 1]);
            float v0 = acc[mb][nb][0] + b0, v1 = acc[mb][nb][1] + b1;
            float v2 = acc[mb][nb][2] + b0, v3 = acc[mb][nb][3] + b1;
            if (MODE == 0) {
                *(float2*)(Cmat + (size_t)row * N + col)       = make_float2(v0, v1);
                *(float2*)(Cmat + (size_t)(row + 8) * N + col) = make_float2(v2, v3);
            } else if (MODE == 1) {
                if (col < C_) { v0 *= 0.125f; v1 *= 0.125f; v2 *= 0.125f; v3 *= 0.125f; }
                uint32_t h01, l01, h23, l23;
                split_pack2(v0, v1, h01, l01);
                split_pack2(v2, v3, h23, l23);
                *(uint32_t*)(Oh + (size_t)row * N + col)       = h01;
                *(uint32_t*)(Oh + (size_t)(row + 8) * N + col) = h23;
                if (col < 2 * C_) {          // lo needed only for Q,K
                    *(uint32_t*)(Ol + (size_t)row * N + col)       = l01;
                    *(uint32_t*)(Ol + (size_t)(row + 8) * N + col) = l23;
                }
            } else {  // MODE 2: gelu -> fp16
                v0 = gelu_exact(v0); v1 = gelu_exact(v1);
                v2 = gelu_exact(v2); v3 = gelu_exact(v3);
                *(uint32_t*)(Oh + (size_t)row * N + col)       = pack_f16x2(v0, v1);
                *(uint32_t*)(Oh + (size_t)(row + 8) * N + col) = pack_f16x2(v2, v3);
            }
        }
    }
}

// ---------------- tensor-core causal flash attention ------------------------
// 128 queries per CTA (8 warps x 16 rows), 64-key tiles.
// S = 3-term split fp16 (Qh*Kh + Ql*Kh + Qh*Kl); PV = single fp16 term.
#define AT_ROWB  144
#define AQ_T     (128 * AT_ROWB)             // 18432 per Q operand
#define AK_T     (64 * AT_ROWB)              // 9216 per K/V operand
#define AT_STAGE (3 * AK_T)                  // Kh,Kl,Vh = 27648
#define AT_SMEM  (2 * AQ_T + 2 * AT_STAGE)   // 92160

__global__ void __launch_bounds__(256, 1) attn_tc(
    const __half* __restrict__ qkvh,
    const __half* __restrict__ qkvl,
    float* __restrict__ y)
{
    extern __shared__ char smem[];
    const uint32_t sb = smem_u32(smem);
    const int tid = threadIdx.x, lane = tid & 31, wid = tid >> 5;
    const int qb = (int)gridDim.x - 1 - (int)blockIdx.x;   // big blocks first
    const int h = blockIdx.y, b = blockIdx.z;
    const int q0 = qb * 128;
    const int wq = wid * 16;
    const int gr = lane >> 2, gc = lane & 3;
    const int RS = 3 * C_;

    const __half* qh = qkvh + (size_t)b * T_ * RS + h * D_;
    const __half* ql = qkvl + (size_t)b * T_ * RS + h * D_;
    const __half* kh = qh + C_;
    const __half* kl = ql + C_;
    const __half* vh = qh + 2 * C_;

    const uint32_t QH  = sb;
    const uint32_t ST0 = sb + 2 * AQ_T;

    // load Q (hi/lo) tile: 128 rows x 128B each
#pragma unroll
    for (int t = 0; t < 2; t++) {
        const __half* g = t ? ql : qh;
#pragma unroll
        for (int i = 0; i < 4; i++) {
            int u = tid + i * 256;          // 0..1023
            int r = u >> 3, c = u & 7;
            CP16(QH + t * AQ_T + r * AT_ROWB + c * 16, g + (size_t)(q0 + r) * RS + c * 8);
        }
    }

    auto load_tile = [&](int kt, int bufsel) {
        uint32_t st = ST0 + bufsel * AT_STAGE;
#pragma unroll
        for (int t = 0; t < 3; t++) {
            const __half* g = (t == 0 ? kh : t == 1 ? kl : vh);
#pragma unroll
            for (int i = 0; i < 2; i++) {
                int u = tid + i * 256;      // 0..511
                int r = u >> 3, c = u & 7;
                CP16(st + t * AK_T + r * AT_ROWB + c * 16, g + (size_t)(kt * 64 + r) * RS + c * 8);
            }
        }
    };
    load_tile(0, 0);
    CP_COMMIT();
    CP_WAIT0();
    __syncthreads();

    // Q fragments
    uint32_t qfh[4][4], qfl[4][4];
    const int a_row = lane & 15, a_off = (lane >> 4) * 16;
#pragma unroll
    for (int ks = 0; ks < 4; ks++) {
        uint32_t ad = QH + (wq + a_row) * AT_ROWB + ks * 32 + a_off;
        ldsm4(qfh[ks][0], qfh[ks][1], qfh[ks][2], qfh[ks][3], ad);
        ldsm4(qfl[ks][0], qfl[ks][1], qfl[ks][2], qfl[ks][3], ad + AQ_T);
    }

    float Oacc[8][4];
#pragma unroll
    for (int i = 0; i < 8; i++)
#pragma unroll
        for (int j = 0; j < 4; j++) Oacc[i][j] = 0.f;
    float m0 = -1e30f, m1 = -1e30f, l0 = 0.f, l1 = 0.f;

    const int nt = 2 * qb + 2;
    const int b_row = (lane & 7) + ((lane >> 4) << 3);
    const int b_off = ((lane >> 3) & 1) * 16;
    const int v_row = (lane & 7) + ((lane >> 3) & 1) * 8;
    const int v_off = (lane >> 4) * 16;

    for (int kt = 0; kt < nt; kt++) {
        if (kt + 1 < nt) { load_tile(kt + 1, (kt + 1) & 1); CP_COMMIT(); }
        const uint32_t st = ST0 + (kt & 1) * AT_STAGE;

        // warp-level skip: keys all strictly above this warp's queries
        const bool active = (kt * 64) <= (q0 + wq + 15);
        if (active) {
            // ---- S = Q @ K^T (3-term split) ----
            float sacc[8][4];
#pragma unroll
            for (int i = 0; i < 8; i++)
#pragma unroll
                for (int j = 0; j < 4; j++) sacc[i][j] = 0.f;

#pragma unroll
            for (int nbp = 0; nbp < 4; nbp++) {
#pragma unroll
                for (int ks = 0; ks < 4; ks++) {
                    uint32_t kd = st + (nbp * 16 + b_row) * AT_ROWB + ks * 32 + b_off;
                    uint32_t rh[4], rl[4];
                    ldsm4(rh[0], rh[1], rh[2], rh[3], kd);
                    ldsm4(rl[0], rl[1], rl[2], rl[3], kd + AK_T);
                    uint32_t b0h[2] = {rh[0], rh[1]}, b1h[2] = {rh[2], rh[3]};
                    uint32_t b0l[2] = {rl[0], rl[1]}, b1l[2] = {rl[2], rl[3]};
                    MMA16816(sacc[2 * nbp],     qfh[ks], b0h);
                    MMA16816(sacc[2 * nbp + 1], qfh[ks], b1h);
                    MMA16816(sacc[2 * nbp],     qfl[ks], b0h);
                    MMA16816(sacc[2 * nbp + 1], qfl[ks], b1h);
                    MMA16816(sacc[2 * nbp],     qfh[ks], b0l);
                    MMA16816(sacc[2 * nbp + 1], qfh[ks], b1l);
                }
            }

            // ---- causal mask (only when tile crosses the diagonal) ----
            if (kt * 64 + 63 > q0 + wq) {
                const int qg0 = q0 + wq + gr, qg1 = qg0 + 8;
#pragma unroll
                for (int nb = 0; nb < 8; nb++) {
                    int kg = kt * 64 + nb * 8 + 2 * gc;
                    if (kg     > qg0) sacc[nb][0] = -1e30f;
                    if (kg + 1 > qg0) sacc[nb][1] = -1e30f;
                    if (kg     > qg1) sacc[nb][2] = -1e30f;
                    if (kg + 1 > qg1) sacc[nb][3] = -1e30f;
                }
            }

            // ---- online softmax ----
            float mx0 = m0, mx1 = m1;
#pragma unroll
            for (int nb = 0; nb < 8; nb++) {
                mx0 = fmaxf(mx0, fmaxf(sacc[nb][0], sacc[nb][1]));
                mx1 = fmaxf(mx1, fmaxf(sacc[nb][2], sacc[nb][3]));
            }
            mx0 = fmaxf(mx0, __shfl_xor_sync(0xffffffffu, mx0, 1));
            mx0 = fmaxf(mx0, __shfl_xor_sync(0xffffffffu, mx0, 2));
            mx1 = fmaxf(mx1, __shfl_xor_sync(0xffffffffu, mx1, 1));
            mx1 = fmaxf(mx1, __shfl_xor_sync(0xffffffffu, mx1, 2));
            float al0 = __expf(m0 - mx0), al1 = __expf(m1 - mx1);
            m0 = mx0; m1 = mx1;
            float ls0 = 0.f, ls1 = 0.f;
#pragma unroll
            for (int nb = 0; nb < 8; nb++) {
                sacc[nb][0] = __expf(sacc[nb][0] - mx0); ls0 += sacc[nb][0];
                sacc[nb][1] = __expf(sacc[nb][1] - mx0); ls0 += sacc[nb][1];
                sacc[nb][2] = __expf(sacc[nb][2] - mx1); ls1 += sacc[nb][2];
                sacc[nb][3] = __expf(sacc[nb][3] - mx1); ls1 += sacc[nb][3];
            }
            l0 = l0 * al0 + ls0;
            l1 = l1 * al1 + ls1;
#pragma unroll
            for (int nb = 0; nb < 8; nb++) {
                Oacc[nb][0] *= al0; Oacc[nb][1] *= al0;
                Oacc[nb][2] *= al1; Oacc[nb][3] *= al1;
            }

            // ---- O += P @ V (single fp16 term) ----
#pragma unroll
            for (int kb = 0; kb < 4; kb++) {
                uint32_t ph[4];
                ph[0] = pack_f16x2(sacc[2 * kb][0],     sacc[2 * kb][1]);
                ph[1] = pack_f16x2(sacc[2 * kb][2],     sacc[2 * kb][3]);
                ph[2] = pack_f16x2(sacc[2 * kb + 1][0], sacc[2 * kb + 1][1]);
                ph[3] = pack_f16x2(sacc[2 * kb + 1][2], sacc[2 * kb + 1][3]);
#pragma unroll
                for (int nbp = 0; nbp < 4; nbp++) {
                    uint32_t vd = st + 2 * AK_T + (kb * 16 + v_row) * AT_ROWB + nbp * 32 + v_off;
                    uint32_t rh[4];
                    ldsm4t(rh[0], rh[1], rh[2], rh[3], vd);
                    uint32_t v0h[2] = {rh[0], rh[1]}, v1h[2] = {rh[2], rh[3]};
                    MMA16816(Oacc[2 * nbp],     ph, v0h);
                    MMA16816(Oacc[2 * nbp + 1], ph, v1h);
                }
            }
        }

        CP_WAIT0();
        __syncthreads();
    }

    // ---- finalize ----
    l0 += __shfl_xor_sync(0xffffffffu, l0, 1);
    l0 += __shfl_xor_sync(0xffffffffu, l0, 2);
    l1 += __shfl_xor_sync(0xffffffffu, l1, 1);
    l1 += __shfl_xor_sync(0xffffffffu, l1, 2);
    const float inv0 = 1.f / l0, inv1 = 1.f / l1;

    float* yb = y + ((size_t)b * T_ + q0 + wq) * C_ + h * D_;
#pragma unroll
    for (int nb = 0; nb < 8; nb++) {
        int col = nb * 8 + 2 * gc;
        *(float2*)(yb + (size_t)gr * C_ + col) =
            make_float2(Oacc[nb][0] * inv0, Oacc[nb][1] * inv0);
        *(float2*)(yb + (size_t)(gr + 8) * C_ + col) =
            make_float2(Oacc[nb][2] * inv1, Oacc[nb][3] * inv1);
    }
}

// ---------------- residual add + LayerNorm (+ optional fp16 out) -----------
template <bool SPLIT>
__global__ void __launch_bounds__(256) add_ln_kernel(
    const float* __restrict__ a, const float* __restrict__ bres,
    const float* __restrict__ g, const float* __restrict__ beta,
    float* __restrict__ out, __half* __restrict__ Oh)
{
    const int row = blockIdx.x;
    const int tid = threadIdx.x;

    const float4 av = ((const float4*)(a    + (size_t)row * C_))[tid];
    const float4 bv = ((const float4*)(bres + (size_t)row * C_))[tid];
    float4 v = make_float4(av.x + bv.x, av.y + bv.y, av.z + bv.z, av.w + bv.w);

    float s  = v.x + v.y + v.z + v.w;
    float sq = v.x * v.x + v.y * v.y + v.z * v.z + v.w * v.w;
#pragma unroll
    for (int off = 16; off; off >>= 1) {
        s  += __shfl_xor_sync(0xffffffffu, s,  off);
        sq += __shfl_xor_sync(0xffffffffu, sq, off);
    }
    __shared__ float ws[8], wsq[8];
    if ((tid & 31) == 0) { ws[tid >> 5] = s; wsq[tid >> 5] = sq; }
    __syncthreads();
    float tot = 0.f, totq = 0.f;
#pragma unroll
    for (int i = 0; i < 8; i++) { tot += ws[i]; totq += wsq[i]; }

    const float mu   = tot * (1.0f / C_);
    const float var  = totq * (1.0f / C_) - mu * mu;
    const float rstd = rsqrtf(var + LN_EPS);

    const float4 gv = ((const float4*)g)[tid];
    const float4 be = ((const float4*)beta)[tid];
    float4 o;
    o.x = (v.x - mu) * rstd * gv.x + be.x;
    o.y = (v.y - mu) * rstd * gv.y + be.y;
    o.z = (v.z - mu) * rstd * gv.z + be.z;
    o.w = (v.w - mu) * rstd * gv.w + be.w;
    ((float4*)(out + (size_t)row * C_))[tid] = o;
    if (SPLIT) {
        uint32_t* oh = (uint32_t*)(Oh + (size_t)row * C_);
        oh[2 * tid]     = pack_f16x2(o.x, o.y);
        oh[2 * tid + 1] = pack_f16x2(o.z, o.w);
    }
}

// ---------------- launcher --------------------------------------------------
extern "C" void kernel_launch(void* const* d_in, const int* in_sizes, int n_in,
                              void* d_out, int out_size)
{
    const float* x     = (const float*)d_in[0];
    const float* w_qkv = (const float*)d_in[1];
    const float* b_qkv = (const float*)d_in[2];
    const float* ln1_g = (const float*)d_in[3];
    const float* ln1_b = (const float*)d_in[4];
    const float* w_fc1 = (const float*)d_in[5];
    const float* b_fc1 = (const float*)d_in[6];
    const float* w_fc2 = (const float*)d_in[7];
    const float* b_fc2 = (const float*)d_in[8];
    const float* ln2_g = (const float*)d_in[9];
    const float* ln2_b = (const float*)d_in[10];
    float* out = (float*)d_out;

    float *att, *x1, *mlp;
    __half *qkvh, *qkvl, *ah, *ah2, *bh;
    cudaGetSymbolAddress((void**)&att,  g_att);
    cudaGetSymbolAddress((void**)&x1,   g_x1);
    cudaGetSymbolAddress((void**)&mlp,  g_mlp);
    cudaGetSymbolAddress((void**)&qkvh, g_qkvh);
    cudaGetSymbolAddress((void**)&qkvl, g_qkvl);
    cudaGetSymbolAddress((void**)&ah,   g_ah);
    cudaGetSymbolAddress((void**)&ah2,  g_ah2);
    cudaGetSymbolAddress((void**)&bh,   g_bh);

    cudaFuncSetAttribute(gemm_mma<0>, cudaFuncAttributeMaxDynamicSharedMemorySize, GM_SMEM);
    cudaFuncSetAttribute(gemm_mma<1>, cudaFuncAttributeMaxDynamicSharedMemorySize, GM_SMEM);
    cudaFuncSetAttribute(gemm_mma<2>, cudaFuncAttributeMaxDynamicSharedMemorySize, GM_SMEM);
    cudaFuncSetAttribute(attn_tc, cudaFuncAttributeMaxDynamicSharedMemorySize, AT_SMEM);

    // ---- QKV = x @ w_qkv + b  -> fp16 (Q scaled 1/8; lo only for Q,K) ----
    round_act<<<(M_ * C_ / 4 + 255) / 256, 256>>>(x, ah, (size_t)M_ * C_ / 4);
    round_w_t<<<dim3(3 * C_ / 32, C_ / 32), dim3(32, 8)>>>(w_qkv, bh, C_, 3 * C_);
    gemm_mma<1><<<dim3(3 * C_ / 128, M_ / 256), 256, GM_SMEM>>>(
        ah, bh, b_qkv, nullptr, qkvh, qkvl, 3 * C_, C_);

    // ---- attention (tensor core, 128 q / CTA) ----
    attn_tc<<<dim3(T_ / 128, H_, B_), 256, AT_SMEM>>>(qkvh, qkvl, att);

    // ---- x1 = LN1(x + att), fused fp16 round for FC1 A ----
    add_ln_kernel<true><<<M_, 256>>>(x, att, ln1_g, ln1_b, x1, ah);

    // ---- h = gelu(x1 @ w_fc1 + b) -> fp16 ----
    round_w_t<<<dim3(4 * C_ / 32, C_ / 32), dim3(32, 8)>>>(w_fc1, bh, C_, 4 * C_);
    gemm_mma<2><<<dim3(4 * C_ / 128, M_ / 256), 256, GM_SMEM>>>(
        ah, bh, b_fc1, nullptr, ah2, nullptr, 4 * C_, C_);

    // ---- mlp = h @ w_fc2 + b (fp32) ----
    round_w_t<<<dim3(C_ / 32, 4 * C_ / 32), dim3(32, 8)>>>(w_fc2, bh, 4 * C_, C_);
    gemm_mma<0><<<dim3(C_ / 128, M_ / 256), 256, GM_SMEM>>>(
        ah2, bh, b_fc2, mlp, nullptr, nullptr, C_, 4 * C_);

    // ---- out = LN2(x1 + mlp) ----
    add_ln_kernel<false><<<M_, 256>>>(x1, mlp, ln2_g, ln2_b, out, nullptr);
}

// round 11
// speedup vs baseline: 1.7330x; 1.0887x over previous
#include <cuda_runtime.h>
#include <cuda_fp16.h>
#include <math.h>
#include <stdint.h>

#define B_   4
#define T_   2048
#define C_   1024
#define H_   16
#define D_   64
#define M_   (B_ * T_)           // 8192 rows
#define LN_EPS 1e-5f

// ---------------- scratch (static device globals; no allocation) -----------
__device__ __align__(128) float g_att[(size_t)M_ * C_];
__device__ __align__(128) float g_x1 [(size_t)M_ * C_];
__device__ __align__(128) float g_mlp[(size_t)M_ * C_];
__device__ __align__(128) __half g_qkvh[(size_t)M_ * 3 * C_];   // fp16 qkv (Q pre-scaled)
__device__ __align__(128) __half g_ah [(size_t)M_ * C_];        // A (x / x1) fp16
__device__ __align__(128) __half g_ah2[(size_t)M_ * 4 * C_];    // gelu(h) fp16
__device__ __align__(128) __half g_bh [(size_t)4 * C_ * C_];    // B [N,K] fp16

__device__ __forceinline__ float gelu_exact(float x) {
    return 0.5f * x * (1.0f + erff(x * 0.70710678118654752440f));
}

// ---------------- PTX helpers ----------------------------------------------
__device__ __forceinline__ uint32_t smem_u32(const void* p) {
    uint32_t a;
    asm("{ .reg .u64 t; cvta.to.shared.u64 t, %1; cvt.u32.u64 %0, t; }" : "=r"(a) : "l"(p));
    return a;
}
#define CP16(s, g) asm volatile("cp.async.cg.shared.global [%0], [%1], 16;" :: "r"(s), "l"(g))
#define CP_COMMIT() asm volatile("cp.async.commit_group;" ::: "memory")
#define CP_WAIT2()  asm volatile("cp.async.wait_group 2;" ::: "memory")
#define CP_WAIT0()  asm volatile("cp.async.wait_group 0;" ::: "memory")

__device__ __forceinline__ void ldsm4(uint32_t& r0, uint32_t& r1,
                                      uint32_t& r2, uint32_t& r3, uint32_t addr) {
    asm volatile("ldmatrix.sync.aligned.m8n8.x4.shared.b16 {%0,%1,%2,%3}, [%4];"
                 : "=r"(r0), "=r"(r1), "=r"(r2), "=r"(r3) : "r"(addr));
}
__device__ __forceinline__ void ldsm4t(uint32_t& r0, uint32_t& r1,
                                       uint32_t& r2, uint32_t& r3, uint32_t addr) {
    asm volatile("ldmatrix.sync.aligned.m8n8.x4.trans.shared.b16 {%0,%1,%2,%3}, [%4];"
                 : "=r"(r0), "=r"(r1), "=r"(r2), "=r"(r3) : "r"(addr));
}
#define MMA16816(c, a, b)                                                     \
    asm("mma.sync.aligned.m16n8k16.row.col.f32.f16.f16.f32 "                  \
        "{%0,%1,%2,%3}, {%4,%5,%6,%7}, {%8,%9}, {%0,%1,%2,%3};"               \
        : "+f"((c)[0]), "+f"((c)[1]), "+f"((c)[2]), "+f"((c)[3])              \
        : "r"((a)[0]), "r"((a)[1]), "r"((a)[2]), "r"((a)[3]),                 \
          "r"((b)[0]), "r"((b)[1]))

__device__ __forceinline__ uint32_t pack_f16x2(float lo, float hi) {
    uint32_t r;
    asm("cvt.rn.f16x2.f32 %0, %1, %2;" : "=r"(r) : "f"(hi), "f"(lo));
    return r;
}

// ---------------- conversion kernels ----------------------------------------
__global__ void __launch_bounds__(256) round_act(
    const float* __restrict__ X, __half* __restrict__ Hh, size_t n4)
{
    size_t i = (size_t)blockIdx.x * blockDim.x + threadIdx.x;
    if (i >= n4) return;
    float4 v = ((const float4*)X)[i];
    ((uint32_t*)Hh)[2 * i]     = pack_f16x2(v.x, v.y);
    ((uint32_t*)Hh)[2 * i + 1] = pack_f16x2(v.z, v.w);
}

// W [K,N] fp32 -> Bh [N,K] fp16 (transpose + single rounding)
__global__ void __launch_bounds__(256) round_w_t(
    const float* __restrict__ W, __half* __restrict__ Bh, int K, int N)
{
    __shared__ float t[32][33];
    const int tx = threadIdx.x, ty = threadIdx.y;   // block (32,8)
    const int n0 = blockIdx.x * 32, k0 = blockIdx.y * 32;
#pragma unroll
    for (int r = 0; r < 4; r++)
        t[ty + r * 8][tx] = W[(size_t)(k0 + ty + r * 8) * N + n0 + tx];
    __syncthreads();
#pragma unroll
    for (int r = 0; r < 4; r++) {
        int nn = ty + r * 8;
        Bh[(size_t)(n0 + nn) * K + k0 + tx] = __float2half_rn(t[tx][nn]);
    }
}

// ---------------- HMMA fp16 GEMM --------------------------------------------
// C = A@B^T + bias  (A, B single-rounded fp16, fp32 accum)
// CTA tile 256x128, warp tile 64x64 (8 warps = 4m x 2n), BK=32, 4 stages.
// MODE 0: fp32 out; MODE 1: fp16 out, cols<C_ scaled 0.125 (QKV);
// MODE 2: gelu then fp16 out.
#define GM_BK     32
#define GM_ROWB   80
#define GM_AOP    (256 * GM_ROWB)             // 20480
#define GM_BOP    (128 * GM_ROWB)             // 10240
#define GM_STAGE  (GM_AOP + GM_BOP)           // 30720
#define GM_SMEM   (4 * GM_STAGE)              // 122880

template <int MODE>
__global__ void __launch_bounds__(256, 1) gemm_mma(
    const __half* __restrict__ Ah, const __half* __restrict__ Bh,
    const float* __restrict__ bias, float* __restrict__ Cmat,
    __half* __restrict__ Oh, int N, int K)
{
    extern __shared__ char smem[];
    const uint32_t sb = smem_u32(smem);
    const int tid  = threadIdx.x;
    const int lane = tid & 31;
    const int wid  = tid >> 5;
    const int m0 = blockIdx.y * 256;
    const int n0 = blockIdx.x * 128;
    const int wm = (wid >> 1) * 64;
    const int wn = (wid & 1) * 64;

    const int nch = K / GM_BK;

    auto load_chunk = [&](int c) {
        const int kk = c * GM_BK;
        const uint32_t st = sb + (c & 3) * GM_STAGE;
#pragma unroll
        for (int i = 0; i < 4; i++) {                // A: 1024 x 16B units
            int u = tid + i * 256;
            int r = u >> 2, cc = u & 3;
            CP16(st + r * GM_ROWB + cc * 16, Ah + (size_t)(m0 + r) * K + kk + cc * 8);
        }
#pragma unroll
        for (int i = 0; i < 2; i++) {                // B: 512 x 16B units
            int u = tid + i * 256;
            int r = u >> 2, cc = u & 3;
            CP16(st + GM_AOP + r * GM_ROWB + cc * 16, Bh + (size_t)(n0 + r) * K + kk + cc * 8);
        }
    };

    float acc[4][8][4];
#pragma unroll
    for (int i = 0; i < 4; i++)
#pragma unroll
        for (int j = 0; j < 8; j++)
#pragma unroll
            for (int t = 0; t < 4; t++) acc[i][j][t] = 0.f;

    load_chunk(0); CP_COMMIT();
    load_chunk(1); CP_COMMIT();
    load_chunk(2); CP_COMMIT();

    const int a_row = lane & 15;
    const int a_off = (lane >> 4) * 16;
    const int b_row = (lane & 7) + ((lane >> 4) << 3);
    const int b_off = ((lane >> 3) & 1) * 16;

    for (int k = 0; k < nch; k++) {
        CP_WAIT2();                       // 3 groups pending -> chunk k resident
        __syncthreads();
        if (k + 3 < nch) load_chunk(k + 3);
        CP_COMMIT();                      // unconditional: keeps pending-count invariant

        const uint32_t stA = sb + (k & 3) * GM_STAGE;
        const uint32_t stB = stA + GM_AOP;

#pragma unroll
        for (int ks = 0; ks < 2; ks++) {
            uint32_t ah[4][4];
#pragma unroll
            for (int mb = 0; mb < 4; mb++) {
                uint32_t ad = stA + (wm + mb * 16 + a_row) * GM_ROWB + ks * 32 + a_off;
                ldsm4(ah[mb][0], ah[mb][1], ah[mb][2], ah[mb][3], ad);
            }
#pragma unroll
            for (int nbp = 0; nbp < 4; nbp++) {
                uint32_t bd = stB + (wn + nbp * 16 + b_row) * GM_ROWB + ks * 32 + b_off;
                uint32_t h0, h1, h2, h3;
                ldsm4(h0, h1, h2, h3, bd);
                uint32_t b0h[2] = {h0, h1}, b1h[2] = {h2, h3};
#pragma unroll
                for (int mb = 0; mb < 4; mb++) MMA16816(acc[mb][2 * nbp],     ah[mb], b0h);
#pragma unroll
                for (int mb = 0; mb < 4; mb++) MMA16816(acc[mb][2 * nbp + 1], ah[mb], b1h);
            }
        }
    }

    // ---- epilogue ----
    const int gr = lane >> 2;
    const int gc = (lane & 3) * 2;
#pragma unroll
    for (int mb = 0; mb < 4; mb++) {
#pragma unroll
        for (int nb = 0; nb < 8; nb++) {
            int row = m0 + wm + mb * 16 + gr;
            int col = n0 + wn + nb * 8 + gc;
            float b0 = __ldg(&bias[col]), b1 = __ldg(&bias[col + 1]);
            float v0 = acc[mb][nb][0] + b0, v1 = acc[mb][nb][1] + b1;
            float v2 = acc[mb][nb][2] + b0, v3 = acc[mb][nb][3] + b1;
            if (MODE == 0) {
                *(float2*)(Cmat + (size_t)row * N + col)       = make_float2(v0, v1);
                *(float2*)(Cmat + (size_t)(row + 8) * N + col) = make_float2(v2, v3);
            } else {
                if (MODE == 1 && col < C_) { v0 *= 0.125f; v1 *= 0.125f; v2 *= 0.125f; v3 *= 0.125f; }
                if (MODE == 2) {
                    v0 = gelu_exact(v0); v1 = gelu_exact(v1);
                    v2 = gelu_exact(v2); v3 = gelu_exact(v3);
                }
                *(uint32_t*)(Oh + (size_t)row * N + col)       = pack_f16x2(v0, v1);
                *(uint32_t*)(Oh + (size_t)(row + 8) * N + col) = pack_f16x2(v2, v3);
            }
        }
    }
}

// ---------------- tensor-core causal flash attention (all fp16) -------------
// 128 queries per CTA (8 warps x 16 rows), 64-key tiles, single-term MMAs.
#define AT_ROWB  144
#define AQ_T     (128 * AT_ROWB)             // 18432 (Q)
#define AK_T     (64 * AT_ROWB)              // 9216 per K/V operand
#define AT_STAGE (2 * AK_T)                  // Kh,Vh = 18432
#define AT_SMEM  (AQ_T + 2 * AT_STAGE)       // 55296

__global__ void __launch_bounds__(256, 1) attn_tc(
    const __half* __restrict__ qkvh, float* __restrict__ y)
{
    extern __shared__ char smem[];
    const uint32_t sb = smem_u32(smem);
    const int tid = threadIdx.x, lane = tid & 31, wid = tid >> 5;
    const int qb = (int)gridDim.x - 1 - (int)blockIdx.x;   // big blocks first
    const int h = blockIdx.y, b = blockIdx.z;
    const int q0 = qb * 128;
    const int wq = wid * 16;
    const int gr = lane >> 2, gc = lane & 3;
    const int RS = 3 * C_;

    const __half* qh = qkvh + (size_t)b * T_ * RS + h * D_;
    const __half* kh = qh + C_;
    const __half* vh = qh + 2 * C_;

    const uint32_t QH  = sb;
    const uint32_t ST0 = sb + AQ_T;

    // load Q tile: 128 rows x 128B
#pragma unroll
    for (int i = 0; i < 4; i++) {
        int u = tid + i * 256;              // 0..1023
        int r = u >> 3, c = u & 7;
        CP16(QH + r * AT_ROWB + c * 16, qh + (size_t)(q0 + r) * RS + c * 8);
    }

    auto load_tile = [&](int kt, int bufsel) {
        uint32_t st = ST0 + bufsel * AT_STAGE;
#pragma unroll
        for (int t = 0; t < 2; t++) {
            const __half* g = (t == 0 ? kh : vh);
#pragma unroll
            for (int i = 0; i < 2; i++) {
                int u = tid + i * 256;      // 0..511
                int r = u >> 3, c = u & 7;
                CP16(st + t * AK_T + r * AT_ROWB + c * 16, g + (size_t)(kt * 64 + r) * RS + c * 8);
            }
        }
    };
    load_tile(0, 0);
    CP_COMMIT();
    CP_WAIT0();
    __syncthreads();

    // Q fragments
    uint32_t qf[4][4];
    const int a_row = lane & 15, a_off = (lane >> 4) * 16;
#pragma unroll
    for (int ks = 0; ks < 4; ks++) {
        uint32_t ad = QH + (wq + a_row) * AT_ROWB + ks * 32 + a_off;
        ldsm4(qf[ks][0], qf[ks][1], qf[ks][2], qf[ks][3], ad);
    }

    float Oacc[8][4];
#pragma unroll
    for (int i = 0; i < 8; i++)
#pragma unroll
        for (int j = 0; j < 4; j++) Oacc[i][j] = 0.f;
    float m0 = -1e30f, m1 = -1e30f, l0 = 0.f, l1 = 0.f;

    const int nt = 2 * qb + 2;
    const int b_row = (lane & 7) + ((lane >> 4) << 3);
    const int b_off = ((lane >> 3) & 1) * 16;
    const int v_row = (lane & 7) + ((lane >> 3) & 1) * 8;
    const int v_off = (lane >> 4) * 16;

    for (int kt = 0; kt < nt; kt++) {
        if (kt + 1 < nt) { load_tile(kt + 1, (kt + 1) & 1); CP_COMMIT(); }
        const uint32_t st = ST0 + (kt & 1) * AT_STAGE;

        // warp-level skip: keys all strictly above this warp's queries
        const bool active = (kt * 64) <= (q0 + wq + 15);
        if (active) {
            // ---- S = Q @ K^T ----
            float sacc[8][4];
#pragma unroll
            for (int i = 0; i < 8; i++)
#pragma unroll
                for (int j = 0; j < 4; j++) sacc[i][j] = 0.f;

#pragma unroll
            for (int nbp = 0; nbp < 4; nbp++) {
#pragma unroll
                for (int ks = 0; ks < 4; ks++) {
                    uint32_t kd = st + (nbp * 16 + b_row) * AT_ROWB + ks * 32 + b_off;
                    uint32_t r0, r1, r2, r3;
                    ldsm4(r0, r1, r2, r3, kd);
                    uint32_t b0[2] = {r0, r1}, b1[2] = {r2, r3};
                    MMA16816(sacc[2 * nbp],     qf[ks], b0);
                    MMA16816(sacc[2 * nbp + 1], qf[ks], b1);
                }
            }

            // ---- causal mask (only when tile crosses the diagonal) ----
            if (kt * 64 + 63 > q0 + wq) {
                const int qg0 = q0 + wq + gr, qg1 = qg0 + 8;
#pragma unroll
                for (int nb = 0; nb < 8; nb++) {
                    int kg = kt * 64 + nb * 8 + 2 * gc;
                    if (kg     > qg0) sacc[nb][0] = -1e30f;
                    if (kg + 1 > qg0) sacc[nb][1] = -1e30f;
                    if (kg     > qg1) sacc[nb][2] = -1e30f;
                    if (kg + 1 > qg1) sacc[nb][3] = -1e30f;
                }
            }

            // ---- online softmax ----
            float mx0 = m0, mx1 = m1;
#pragma unroll
            for (int nb = 0; nb < 8; nb++) {
                mx0 = fmaxf(mx0, fmaxf(sacc[nb][0], sacc[nb][1]));
                mx1 = fmaxf(mx1, fmaxf(sacc[nb][2], sacc[nb][3]));
            }
            mx0 = fmaxf(mx0, __shfl_xor_sync(0xffffffffu, mx0, 1));
            mx0 = fmaxf(mx0, __shfl_xor_sync(0xffffffffu, mx0, 2));
            mx1 = fmaxf(mx1, __shfl_xor_sync(0xffffffffu, mx1, 1));
            mx1 = fmaxf(mx1, __shfl_xor_sync(0xffffffffu, mx1, 2));
            float al0 = __expf(m0 - mx0), al1 = __expf(m1 - mx1);
            m0 = mx0; m1 = mx1;
            float ls0 = 0.f, ls1 = 0.f;
#pragma unroll
            for (int nb = 0; nb < 8; nb++) {
                sacc[nb][0] = __expf(sacc[nb][0] - mx0); ls0 += sacc[nb][0];
                sacc[nb][1] = __expf(sacc[nb][1] - mx0); ls0 += sacc[nb][1];
                sacc[nb][2] = __expf(sacc[nb][2] - mx1); ls1 += sacc[nb][2];
                sacc[nb][3] = __expf(sacc[nb][3] - mx1); ls1 += sacc[nb][3];
            }
            l0 = l0 * al0 + ls0;
            l1 = l1 * al1 + ls1;
#pragma unroll
            for (int nb = 0; nb < 8; nb++) {
                Oacc[nb][0] *= al0; Oacc[nb][1] *= al0;
                Oacc[nb][2] *= al1; Oacc[nb][3] *= al1;
            }

            // ---- O += P @ V ----
#pragma unroll
            for (int kb = 0; kb < 4; kb++) {
                uint32_t ph[4];
                ph[0] = pack_f16x2(sacc[2 * kb][0],     sacc[2 * kb][1]);
                ph[1] = pack_f16x2(sacc[2 * kb][2],     sacc[2 * kb][3]);
                ph[2] = pack_f16x2(sacc[2 * kb + 1][0], sacc[2 * kb + 1][1]);
                ph[3] = pack_f16x2(sacc[2 * kb + 1][2], sacc[2 * kb + 1][3]);
#pragma unroll
                for (int nbp = 0; nbp < 4; nbp++) {
                    uint32_t vd = st + AK_T + (kb * 16 + v_row) * AT_ROWB + nbp * 32 + v_off;
                    uint32_t r0, r1, r2, r3;
                    ldsm4t(r0, r1, r2, r3, vd);
                    uint32_t v0[2] = {r0, r1}, v1[2] = {r2, r3};
                    MMA16816(Oacc[2 * nbp],     ph, v0);
                    MMA16816(Oacc[2 * nbp + 1], ph, v1);
                }
            }
        }

        CP_WAIT0();
        __syncthreads();
    }

    // ---- finalize ----
    l0 += __shfl_xor_sync(0xffffffffu, l0, 1);
    l0 += __shfl_xor_sync(0xffffffffu, l0, 2);
    l1 += __shfl_xor_sync(0xffffffffu, l1, 1);
    l1 += __shfl_xor_sync(0xffffffffu, l1, 2);
    const float inv0 = 1.f / l0, inv1 = 1.f / l1;

    float* yb = y + ((size_t)b * T_ + q0 + wq) * C_ + h * D_;
#pragma unroll
    for (int nb = 0; nb < 8; nb++) {
        int col = nb * 8 + 2 * gc;
        *(float2*)(yb + (size_t)gr * C_ + col) =
            make_float2(Oacc[nb][0] * inv0, Oacc[nb][1] * inv0);
        *(float2*)(yb + (size_t)(gr + 8) * C_ + col) =
            make_float2(Oacc[nb][2] * inv1, Oacc[nb][3] * inv1);
    }
}

// ---------------- residual add + LayerNorm (+ optional fp16 out) -----------
template <bool SPLIT>
__global__ void __launch_bounds__(256) add_ln_kernel(
    const float* __restrict__ a, const float* __restrict__ bres,
    const float* __restrict__ g, const float* __restrict__ beta,
    float* __restrict__ out, __half* __restrict__ Oh)
{
    const int row = blockIdx.x;
    const int tid = threadIdx.x;

    const float4 av = ((const float4*)(a    + (size_t)row * C_))[tid];
    const float4 bv = ((const float4*)(bres + (size_t)row * C_))[tid];
    float4 v = make_float4(av.x + bv.x, av.y + bv.y, av.z + bv.z, av.w + bv.w);

    float s  = v.x + v.y + v.z + v.w;
    float sq = v.x * v.x + v.y * v.y + v.z * v.z + v.w * v.w;
#pragma unroll
    for (int off = 16; off; off >>= 1) {
        s  += __shfl_xor_sync(0xffffffffu, s,  off);
        sq += __shfl_xor_sync(0xffffffffu, sq, off);
    }
    __shared__ float ws[8], wsq[8];
    if ((tid & 31) == 0) { ws[tid >> 5] = s; wsq[tid >> 5] = sq; }
    __syncthreads();
    float tot = 0.f, totq = 0.f;
#pragma unroll
    for (int i = 0; i < 8; i++) { tot += ws[i]; totq += wsq[i]; }

    const float mu   = tot * (1.0f / C_);
    const float var  = totq * (1.0f / C_) - mu * mu;
    const float rstd = rsqrtf(var + LN_EPS);

    const float4 gv = ((const float4*)g)[tid];
    const float4 be = ((const float4*)beta)[tid];
    float4 o;
    o.x = (v.x - mu) * rstd * gv.x + be.x;
    o.y = (v.y - mu) * rstd * gv.y + be.y;
    o.z = (v.z - mu) * rstd * gv.z + be.z;
    o.w = (v.w - mu) * rstd * gv.w + be.w;
    ((float4*)(out + (size_t)row * C_))[tid] = o;
    if (SPLIT) {
        uint32_t* oh = (uint32_t*)(Oh + (size_t)row * C_);
        oh[2 * tid]     = pack_f16x2(o.x, o.y);
        oh[2 * tid + 1] = pack_f16x2(o.z, o.w);
    }
}

// ---------------- launcher --------------------------------------------------
extern "C" void kernel_launch(void* const* d_in, const int* in_sizes, int n_in,
                              void* d_out, int out_size)
{
    const float* x     = (const float*)d_in[0];
    const float* w_qkv = (const float*)d_in[1];
    const float* b_qkv = (const float*)d_in[2];
    const float* ln1_g = (const float*)d_in[3];
    const float* ln1_b = (const float*)d_in[4];
    const float* w_fc1 = (const float*)d_in[5];
    const float* b_fc1 = (const float*)d_in[6];
    const float* w_fc2 = (const float*)d_in[7];
    const float* b_fc2 = (const float*)d_in[8];
    const float* ln2_g = (const float*)d_in[9];
    const float* ln2_b = (const float*)d_in[10];
    float* out = (float*)d_out;

    float *att, *x1, *mlp;
    __half *qkvh, *ah, *ah2, *bh;
    cudaGetSymbolAddress((void**)&att,  g_att);
    cudaGetSymbolAddress((void**)&x1,   g_x1);
    cudaGetSymbolAddress((void**)&mlp,  g_mlp);
    cudaGetSymbolAddress((void**)&qkvh, g_qkvh);
    cudaGetSymbolAddress((void**)&ah,   g_ah);
    cudaGetSymbolAddress((void**)&ah2,  g_ah2);
    cudaGetSymbolAddress((void**)&bh,   g_bh);

    cudaFuncSetAttribute(gemm_mma<0>, cudaFuncAttributeMaxDynamicSharedMemorySize, GM_SMEM);
    cudaFuncSetAttribute(gemm_mma<1>, cudaFuncAttributeMaxDynamicSharedMemorySize, GM_SMEM);
    cudaFuncSetAttribute(gemm_mma<2>, cudaFuncAttributeMaxDynamicSharedMemorySize, GM_SMEM);
    cudaFuncSetAttribute(attn_tc, cudaFuncAttributeMaxDynamicSharedMemorySize, AT_SMEM);

    // ---- QKV = x @ w_qkv + b  -> fp16 (Q scaled 1/8) ----
    round_act<<<(M_ * C_ / 4 + 255) / 256, 256>>>(x, ah, (size_t)M_ * C_ / 4);
    round_w_t<<<dim3(3 * C_ / 32, C_ / 32), dim3(32, 8)>>>(w_qkv, bh, C_, 3 * C_);
    gemm_mma<1><<<dim3(3 * C_ / 128, M_ / 256), 256, GM_SMEM>>>(
        ah, bh, b_qkv, nullptr, qkvh, 3 * C_, C_);

    // ---- attention (tensor core, all fp16, 128 q / CTA) ----
    attn_tc<<<dim3(T_ / 128, H_, B_), 256, AT_SMEM>>>(qkvh, att);

    // ---- x1 = LN1(x + att), fused fp16 round for FC1 A ----
    add_ln_kernel<true><<<M_, 256>>>(x, att, ln1_g, ln1_b, x1, ah);

    // ---- h = gelu(x1 @ w_fc1 + b) -> fp16 ----
    round_w_t<<<dim3(4 * C_ / 32, C_ / 32), dim3(32, 8)>>>(w_fc1, bh, C_, 4 * C_);
    gemm_mma<2><<<dim3(4 * C_ / 128, M_ / 256), 256, GM_SMEM>>>(
        ah, bh, b_fc1, nullptr, ah2, 4 * C_, C_);

    // ---- mlp = h @ w_fc2 + b (fp32) ----
    round_w_t<<<dim3(C_ / 32, 4 * C_ / 32), dim3(32, 8)>>>(w_fc2, bh, 4 * C_, C_);
    gemm_mma<0><<<dim3(C_ / 128, M_ / 256), 256, GM_SMEM>>>(
        ah2, bh, b_fc2, mlp, nullptr, C_, 4 * C_);

    // ---- out = LN2(x1 + mlp) ----
    add_ln_kernel<false><<<M_, 256>>>(x1, mlp, ln2_g, ln2_b, out, nullptr);
}